// round 14
// baseline (speedup 1.0000x reference)
#include <cuda_runtime.h>
#include <cuda_bf16.h>
#include <cstdint>

#define BB 4
#define CIN 128
#define CO 64
#define HH 128
#define WW 128
#define HW (HH*WW)

#define PW 136
#define PH 130
#define PPLANE (PH*PW)
#define QW 68                    // float2 pairs per row
#define QPLANE (PH*QW)           // 8840 float2 per plane

#define PLANE_WW 80
#define PLANE_RR 142
#define PLANE_SZ (PLANE_RR*PLANE_WW)

typedef unsigned long long u64;
typedef unsigned int u32;

__device__ __forceinline__ u32 smem_to_u32(const void* p) {
    u32 a; asm("{ .reg .u64 t; cvta.to.shared.u64 t, %1; cvt.u32.u64 %0, t; }" : "=r"(a) : "l"(p));
    return a;
}

#define MMA_BF16(d0,d1,d2,d3,a0,a1,a2,a3,b0,b1) \
    asm volatile("mma.sync.aligned.m16n8k16.row.col.f32.bf16.bf16.f32 " \
        "{%0,%1,%2,%3},{%4,%5,%6,%7},{%8,%9},{%0,%1,%2,%3};" \
        : "+f"(d0),"+f"(d1),"+f"(d2),"+f"(d3) \
        : "r"(a0),"r"(a1),"r"(a2),"r"(a3),"r"(b0),"r"(b1))

#define LDMATRIX_X4_TRANS(r0,r1,r2,r3,addr) \
    asm volatile("ldmatrix.sync.aligned.m8n8.x4.trans.shared.b16 {%0,%1,%2,%3},[%4];" \
        : "=r"(r0),"=r"(r1),"=r"(r2),"=r"(r3) : "r"(addr))

#define CVT_BF16X2(res, hi_f, lo_f) \
    asm("cvt.rn.bf16x2.f32 %0, %1, %2;" : "=r"(res) : "f"(hi_f), "f"(lo_f))

// ================= scratch =================
__device__ u32    g_xs [2*2*4*128*PLANE_SZ];
__device__ u32    g_wfA[4*72*8*32*4];
__device__ u32    g_dwf[36*8*32*4];
__device__ u32    g_pwf[36*4*32*4];
__device__ u32    g_cwf[16*8*32*4];
__device__ float  g_bias[4*64];
__device__ float  g_yp [16*64*PPLANE];
__device__ float2 g_yp1[16*64*QPLANE];      // odd-phase pair view of g_yp
__device__ float  g_off[16*18*HW];
__device__ u32    g_fs [2*4*256*8192];

// ================= prep (merged) =================
__global__ void prep_kernel(const float* __restrict__ x,
                            const float* __restrict__ w1, const float* __restrict__ w2,
                            const float* __restrict__ w3, const float* __restrict__ w4,
                            const float* __restrict__ pw, const float* __restrict__ dwp,
                            const float* __restrict__ cwp,
                            const float* __restrict__ b1, const float* __restrict__ b2,
                            const float* __restrict__ b3, const float* __restrict__ b4)
{
    int tid = blockIdx.x*blockDim.x + threadIdx.x;
    int nt  = gridDim.x*blockDim.x;
    const float* wb[4] = {w1,w2,w3,w4};
    const float* bbv[4] = {b1,b2,b3,b4};

    for (int i = tid; i < 4*72*8*32*4; i += nt) {
        int br = i / 73728; int r2 = i % 73728;
        int ks = r2 >> 10;  int r3 = r2 & 1023;
        int mb = r3 >> 7;   int lane = (r3 >> 2) & 31; int reg = r3 & 3;
        int row = mb*16 + (lane>>2) + (reg&1)*8;
        int k0  = (lane&3)*2 + (reg>>1)*8;
        int oc = row & 63, split = row >> 6;
        int tap = ks >> 3;
        int ic0 = (ks & 7)*16;
        u32 out = 0;
        #pragma unroll
        for (int e = 0; e < 2; e++) {
            float W = wb[br][oc*1152 + (ic0 + k0 + e)*9 + tap];
            __nv_bfloat16 hi = __float2bfloat16(W);
            __nv_bfloat16 v = split ? __float2bfloat16(W - __bfloat162float(hi)) : hi;
            out |= (u32)__bfloat16_as_ushort(v) << (16*e);
        }
        g_wfA[i] = out;
    }
    for (int i = tid; i < 36*8*32*4; i += nt) {
        int ks = i >> 10; int r3 = i & 1023;
        int mb = r3 >> 7; int lane = (r3 >> 2) & 31; int reg = r3 & 3;
        int row = mb*16 + (lane>>2) + (reg&1)*8;
        int k0  = ks*16 + (lane&3)*2 + (reg>>1)*8;
        int oc = row & 63, split = row >> 6;
        u32 out = 0;
        #pragma unroll
        for (int e = 0; e < 2; e++) {
            int k = k0 + e; int c = k & 63; int n = k >> 6;
            float W = dwp[oc*576 + c*9 + n];
            __nv_bfloat16 hi = __float2bfloat16(W);
            __nv_bfloat16 v = split ? __float2bfloat16(W - __bfloat162float(hi)) : hi;
            out |= (u32)__bfloat16_as_ushort(v) << (16*e);
        }
        g_dwf[i] = out;
    }
    for (int i = tid; i < 36*4*32*4; i += nt) {
        int ks = i >> 9; int r3 = i & 511;
        int mb = r3 >> 7; int lane = (r3 >> 2) & 31; int reg = r3 & 3;
        int row = mb*16 + (lane>>2) + (reg&1)*8;
        int k0  = (lane&3)*2 + (reg>>1)*8;
        int oc = row & 31, split = row >> 5;
        int tap = ks >> 2;
        int ic0 = (ks & 3)*16;
        u32 out = 0;
        #pragma unroll
        for (int e = 0; e < 2; e++) {
            float W = (oc < 18) ? pw[oc*576 + (ic0 + k0 + e)*9 + tap] : 0.f;
            __nv_bfloat16 hi = __float2bfloat16(W);
            __nv_bfloat16 v = split ? __float2bfloat16(W - __bfloat162float(hi)) : hi;
            out |= (u32)__bfloat16_as_ushort(v) << (16*e);
        }
        g_pwf[i] = out;
    }
    for (int i = tid; i < 16*8*32*4; i += nt) {
        int ks = i >> 10; int r3 = i & 1023;
        int mb = r3 >> 7; int lane = (r3 >> 2) & 31; int reg = r3 & 3;
        int row = mb*16 + (lane>>2) + (reg&1)*8;
        int k0  = ks*16 + (lane&3)*2 + (reg>>1)*8;
        int oc = row & 63, split = row >> 6;
        u32 out = 0;
        #pragma unroll
        for (int e = 0; e < 2; e++) {
            float W = cwp[oc*256 + k0 + e];
            __nv_bfloat16 hi = __float2bfloat16(W);
            __nv_bfloat16 v = split ? __float2bfloat16(W - __bfloat162float(hi)) : hi;
            out |= (u32)__bfloat16_as_ushort(v) << (16*e);
        }
        g_cwf[i] = out;
    }
    for (int i = tid; i < 256; i += nt) g_bias[i] = bbv[i>>6][i&63];
    for (int i = tid; i < 1024*528; i += nt) {
        int p = i/528; int j = i - p*528;
        int r, c;
        if (j < 136)      { r = 0;       c = j; }
        else if (j < 272) { r = 129;     c = j - 136; }
        else if (j < 400) { r = j - 271; c = 3; }
        else              { r = j - 399; c = 132; }
        g_yp[(size_t)p*PPLANE + r*PW + c] = 0.f;
    }
    // x split/phase planes (both splits per thread)
    {
        size_t total = (size_t)2*4*128*PLANE_SZ;
        for (size_t i = tid; i < total; i += nt) {
            int wd = (int)(i % PLANE_WW); size_t t = i / PLANE_WW;
            int rr = (int)(t % PLANE_RR); t /= PLANE_RR;
            int ic = (int)(t % 128); t /= 128;
            int b  = (int)(t % 4);   t /= 4;
            int phase = (int)t;
            int row = rr - 7;
            int pxa = 2*wd + phase - 8;
            float va = 0.f, vb = 0.f;
            if ((unsigned)row < 128u) {
                const float* xr = x + ((size_t)(b*128+ic)*128 + row)*128;
                if ((unsigned)pxa < 128u)     va = xr[pxa];
                if ((unsigned)(pxa+1) < 128u) vb = xr[pxa+1];
            }
            u32 hi; CVT_BF16X2(hi, vb, va);
            float fhlo = __uint_as_float(hi << 16);
            float fhhi = __uint_as_float(hi & 0xFFFF0000u);
            u32 lo; CVT_BF16X2(lo, vb - fhhi, va - fhlo);
            size_t off = (size_t)rr*PLANE_WW + wd;
            size_t p0 = (size_t)((phase*4 + b)*128 + ic)*PLANE_SZ;
            size_t p1 = (size_t)(((2 + phase)*4 + b)*128 + ic)*PLANE_SZ;
            g_xs[p0 + off] = hi;
            g_xs[p1 + off] = lo;
        }
    }
}

// ================= branch conv (R5 proven form) =================
__global__ void __launch_bounds__(256,2) bconv_kernel()
{
    __shared__ __align__(16) char sraw[33280];
    u32 sb = smem_to_u32(sraw);

    int tid = threadIdx.x, wid = tid>>5, lane = tid&31;
    int wm = wid & 3, nw = wid >> 2;
    int h = blockIdx.x, br = blockIdx.y, b = blockIdx.z;
    int D = 2*br + 1; float scale = (float)D;
    bool is_wh = (wm < 2);

    float acc[2][8][4];
    #pragma unroll
    for (int mi = 0; mi < 2; mi++)
        #pragma unroll
        for (int ni = 0; ni < 8; ni++)
            #pragma unroll
            for (int r = 0; r < 4; r++) acc[mi][ni][r] = 0.f;

    int lm_mat = lane >> 3, lm_row = lane & 7;
    int lm_k = (lm_mat & 1)*8 + lm_row;
    int lm_noff = (lm_mat >> 1)*8;

    auto loadB = [&](int ks, int buf) {
        int tap = ks >> 3, icc = ks & 7;
        int ky = tap/3 - 1, kx = tap - (tap/3)*3 - 1;
        int s = kx*D;
        int phase = (s + 8) & 1;
        int wd0 = (s + 8 - phase) >> 1;
        int srow = h + ky*D + 7;
        char* dst = sraw + buf*8704;
        #pragma unroll
        for (int i = 0; i < 8; i++) {
            int idx = tid + 256*i;
            int split = idx >> 10; int rem = idx & 1023;
            int ic = rem >> 6; int j = rem & 63;
            const u32* p = g_xs + ((size_t)((split*2+phase)*4 + b)*128 + icc*16 + ic)*PLANE_SZ
                         + (size_t)srow*PLANE_WW + wd0 + j;
            u32 v = __ldg(p);
            *(u32*)(dst + split*4352 + ic*272 + j*4) = v;
        }
    };

    loadB(0, 0);
    __syncthreads();

    for (int ks = 0; ks < 72; ks++) {
        int buf = ks & 1;
        if (ks + 1 < 72) loadB(ks+1, buf^1);

        u32 a0[2][4];
        {
            const uint4* ap = (const uint4*)(g_wfA + (((size_t)(br*72 + ks)*8 + wm*2)*32 + lane)*4);
            uint4 f0 = ap[0];
            uint4 f1 = ap[32];
            a0[0][0]=f0.x; a0[0][1]=f0.y; a0[0][2]=f0.z; a0[0][3]=f0.w;
            a0[1][0]=f1.x; a0[1][1]=f1.y; a0[1][2]=f1.z; a0[1][3]=f1.w;
        }

        int nsplits = is_wh ? 2 : 1;
        for (int sp = 0; sp < nsplits; sp++) {
            u32 bf[8][2];
            u32 base = sb + buf*8704 + sp*4352 + lm_k*272;
            #pragma unroll
            for (int li = 0; li < 4; li++) {
                int n = nw*64 + li*16 + lm_noff;
                u32 r0,r1,r2,r3;
                LDMATRIX_X4_TRANS(r0,r1,r2,r3, base + n*2);
                bf[2*li][0]=r0; bf[2*li][1]=r1; bf[2*li+1][0]=r2; bf[2*li+1][1]=r3;
            }
            #pragma unroll
            for (int mi = 0; mi < 2; mi++)
                #pragma unroll
                for (int ni = 0; ni < 8; ni++)
                    MMA_BF16(acc[mi][ni][0],acc[mi][ni][1],acc[mi][ni][2],acc[mi][ni][3],
                             a0[mi][0],a0[mi][1],a0[mi][2],a0[mi][3],
                             bf[ni][0],bf[ni][1]);
        }
        __syncthreads();
    }

    float* epi = (float*)sraw;
    if (!is_wh) {
        int pair = nw*2 + (wm - 2);
        #pragma unroll
        for (int mi = 0; mi < 2; mi++)
            #pragma unroll
            for (int ni = 0; ni < 8; ni++)
                *(float4*)&epi[pair*2048 + (mi*8+ni)*128 + lane*4] = *(float4*)acc[mi][ni];
    }
    __syncthreads();
    if (is_wh) {
        int pair = nw*2 + wm;
        int bi = br*4 + b;
        #pragma unroll
        for (int mi = 0; mi < 2; mi++) {
            #pragma unroll
            for (int ni = 0; ni < 8; ni++) {
                float4 part = *(float4*)&epi[pair*2048 + (mi*8+ni)*128 + lane*4];
                int oc = wm*32 + mi*16 + (lane>>2);
                int px = nw*64 + ni*8 + (lane&3)*2;
                float bb0 = g_bias[br*64 + oc];
                float bb8 = g_bias[br*64 + oc + 8];
                float* p0 = g_yp + ((size_t)(bi*64 + oc))*PPLANE + (size_t)(h+1)*PW + px + 4;
                float* p8 = p0 + (size_t)8*PPLANE;
                float2 o0, o8;
                o0.x = (acc[mi][ni][0] + part.x + bb0)*scale;
                o0.y = (acc[mi][ni][1] + part.y + bb0)*scale;
                o8.x = (acc[mi][ni][2] + part.z + bb8)*scale;
                o8.y = (acc[mi][ni][3] + part.w + bb8)*scale;
                *(float2*)p0 = o0;
                *(float2*)p8 = o8;
            }
        }
    }
}

// ================= ypair: build odd-phase float2 view of g_yp =================
// thread -> 4 consecutive pairs of one (plane,row)
__global__ void ypair_kernel()
{
    int idx = blockIdx.x*blockDim.x + threadIdx.x;
    if (idx >= 1024*130*17) return;
    int quad = idx % 17; int t = idx / 17;
    int row = t % 130;   int plane = t / 130;
    const float* src = g_yp + (size_t)plane*PPLANE + (size_t)row*PW;
    float2* dst = g_yp1 + (size_t)plane*QPLANE + (size_t)row*QW;
    int k0 = quad*4;
    float4 a = *(const float4*)(src + 2*k0);
    float4 bq = *(const float4*)(src + 2*k0 + 4);
    float nx = (2*k0 + 8 < PW) ? src[2*k0 + 8] : 0.f;
    dst[k0+0] = make_float2(a.y,  a.z);
    dst[k0+1] = make_float2(a.w,  bq.x);
    dst[k0+2] = make_float2(bq.y, bq.z);
    dst[k0+3] = make_float2(bq.w, nx);
}

// ================= offset conv via MMA (R9 proven 2-split form) =================
__global__ void __launch_bounds__(256,3) offconv_kernel(const float* __restrict__ pb)
{
    __shared__ __align__(16) char sraw[17408];
    u32 sb = smem_to_u32(sraw);

    int tid = threadIdx.x, wid = tid>>5, lane = tid&31;
    int wm = wid & 3, nw = wid >> 2;
    int h = blockIdx.x, bi = blockIdx.y;
    bool is_wh = (wm < 2);

    float acc[8][4];
    #pragma unroll
    for (int ni = 0; ni < 8; ni++)
        #pragma unroll
        for (int r = 0; r < 4; r++) acc[ni][r] = 0.f;

    int lm_mat = lane >> 3, lm_row = lane & 7;
    int lm_k = (lm_mat & 1)*8 + lm_row;
    int lm_noff = (lm_mat >> 1)*8;

    const float* ypb = g_yp + (size_t)(bi*64)*PPLANE;

    auto loadB = [&](int ks, int buf) {
        int tap = ks >> 2, icc = ks & 3;
        int ky = tap/3 - 1, kx = tap - (tap/3)*3 - 1;
        int srow = h + ky + 1;
        char* dst = sraw + buf*8704;
        #pragma unroll
        for (int i = 0; i < 4; i++) {
            int idx = tid + 256*i;
            int ic = idx >> 6; int j = idx & 63;
            const float* rp = ypb + (size_t)(icc*16 + ic)*PPLANE
                            + (size_t)srow*PW + 2*j + kx + 4;
            float f0 = rp[0], f1 = rp[1];
            u32 hi; CVT_BF16X2(hi, f1, f0);
            float fh0 = __uint_as_float(hi << 16);
            float fh1 = __uint_as_float(hi & 0xFFFF0000u);
            u32 lo; CVT_BF16X2(lo, f1 - fh1, f0 - fh0);
            *(u32*)(dst + ic*272 + j*4) = hi;
            *(u32*)(dst + 4352 + ic*272 + j*4) = lo;
        }
    };

    loadB(0, 0);
    __syncthreads();

    for (int ks = 0; ks < 36; ks++) {
        int buf = ks & 1;
        if (ks + 1 < 36) loadB(ks+1, buf^1);

        u32 a0[4];
        {
            const uint4* ap = (const uint4*)(g_pwf + (((size_t)ks*4 + wm)*32 + lane)*4);
            uint4 f0 = ap[0];
            a0[0]=f0.x; a0[1]=f0.y; a0[2]=f0.z; a0[3]=f0.w;
        }

        int nsplits = is_wh ? 2 : 1;
        for (int sp = 0; sp < nsplits; sp++) {
            u32 bf[8][2];
            u32 base = sb + buf*8704 + sp*4352 + lm_k*272;
            #pragma unroll
            for (int li = 0; li < 4; li++) {
                int n = nw*64 + li*16 + lm_noff;
                u32 r0,r1,r2,r3;
                LDMATRIX_X4_TRANS(r0,r1,r2,r3, base + n*2);
                bf[2*li][0]=r0; bf[2*li][1]=r1; bf[2*li+1][0]=r2; bf[2*li+1][1]=r3;
            }
            #pragma unroll
            for (int ni = 0; ni < 8; ni++)
                MMA_BF16(acc[ni][0],acc[ni][1],acc[ni][2],acc[ni][3],
                         a0[0],a0[1],a0[2],a0[3],
                         bf[ni][0],bf[ni][1]);
        }
        __syncthreads();
    }

    float* epi = (float*)sraw;
    if (!is_wh) {
        int pair = nw*2 + (wm - 2);
        #pragma unroll
        for (int ni = 0; ni < 8; ni++)
            *(float4*)&epi[pair*1024 + ni*128 + lane*4] = *(float4*)acc[ni];
    }
    __syncthreads();
    if (is_wh) {
        int pair = nw*2 + wm;
        #pragma unroll
        for (int ni = 0; ni < 8; ni++) {
            float4 part = *(float4*)&epi[pair*1024 + ni*128 + lane*4];
            int oc = wm*16 + (lane>>2);
            int px = nw*64 + ni*8 + (lane&3)*2;
            if (oc < 18) {
                float bb = pb[oc];
                float2 o;
                o.x = acc[ni][0] + part.x + bb;
                o.y = acc[ni][1] + part.y + bb;
                *(float2*)&g_off[((size_t)(bi*18 + oc))*HW + h*WW + px] = o;
            }
            int oc8 = oc + 8;
            if (oc8 < 18) {
                float bb = pb[oc8];
                float2 o;
                o.x = acc[ni][2] + part.z + bb;
                o.y = acc[ni][3] + part.w + bb;
                *(float2*)&g_off[((size_t)(bi*18 + oc8))*HW + h*WW + px] = o;
            }
        }
    }
}

// ================= deform: pair-gather (1 LDG.64 per tap) + MMA =================
__global__ void __launch_bounds__(256,3) deform_kernel(const float* __restrict__ db)
{
    __shared__ int2   sidx2[576*2];
    __shared__ __align__(16) float4 sgw[576];
    __shared__ __align__(16) u32 smp[2*64*36];
    u32 sb_smp = smem_to_u32(smp);

    int tid = threadIdx.x, wid = tid>>5, lane = tid&31;
    int wm = wid & 3, nw = wid >> 2;
    int w0 = blockIdx.x*64;
    int h  = blockIdx.y;
    int bi = blockIdx.z;
    int br = bi >> 2, b = bi & 3;
    bool is_wh = (wm < 2);

    #pragma unroll 1
    for (int t = tid; t < 576; t += 256) {
        int n = t >> 6, px = t & 63;
        int ny = (n*11) >> 5;
        int nx = n - ny*3;
        int wg = w0 + px;
        const float* offp = g_off + (((size_t)(bi*18 + n))*HH + h)*WW + wg;
        float offy = offp[0];
        float offx = offp[9*HW];
        float py  = (float)(h + 1)  + (float)ny - 1.f + offy;
        float pxx = (float)(wg + 1) + (float)nx - 1.f + offx;
        float fy = floorf(py), fx = floorf(pxx);
        float pyc = fminf(fmaxf(py,  0.f), 129.f);
        float pxc = fminf(fmaxf(pxx, 0.f), 129.f);
        float lty = fminf(fmaxf(fy,       0.f), 129.f);
        float rby = fminf(fmaxf(fy + 1.f, 0.f), 129.f);
        float ltx = fminf(fmaxf(fx,       0.f), 129.f);
        float rbx = fminf(fmaxf(fx + 1.f, 0.f), 129.f);
        float gy1 = 1.f + (lty - pyc), gy2 = 1.f - (rby - pyc);
        float gx1 = 1.f + (ltx - pxc), gx2 = 1.f - (rbx - pxc);
        if (!(fx >= 0.f && fx <= 128.f)) { gx1 = 0.f; gx2 = 0.f; }
        int x0b = min(max((int)fx, 0), 128);
        int y0 = (int)lty, y1 = (int)rby;
        int col = x0b + 3;
        int p = col & 1;
        int kp = col >> 1;
        sidx2[t] = make_int2(((y0*QW + kp) << 1) | p, ((y1*QW + kp) << 1) | p);
        sgw[t] = make_float4(gy1*gx1, gy1*gx2, gy2*gx1, gy2*gx2);
    }

    int lm_mat = lane >> 3, lm_row = lane & 7;
    int lm_k = (lm_mat & 1)*8 + lm_row;
    int lm_noff = (lm_mat >> 1)*8;

    float acc[2][4][4];
    #pragma unroll
    for (int mi = 0; mi < 2; mi++)
        #pragma unroll
        for (int ni = 0; ni < 4; ni++)
            #pragma unroll
            for (int r = 0; r < 4; r++) acc[mi][ni][r] = 0.f;

    const float2* yq0 = (const float2*)(g_yp + (size_t)bi*CO*PPLANE);
    const float2* yq1 = g_yp1 + (size_t)bi*CO*QPLANE;
    __syncthreads();

    for (int n = 0; n < 9; n++) {
        #pragma unroll 1
        for (int u = tid; u < 2048; u += 256) {
            int cc = u >> 5, pxw = u & 31;
            int t = n*64 + pxw*2;
            const float2* b0 = yq0 + (size_t)cc*QPLANE;
            const float2* b1 = yq1 + (size_t)cc*QPLANE;
            int2 i0 = sidx2[t];     float4 g0 = sgw[t];
            int2 i1 = sidx2[t+1];   float4 g1 = sgw[t+1];
            const float2* s0 = (i0.x & 1) ? b1 : b0;
            const float2* s1 = (i1.x & 1) ? b1 : b0;
            float2 T0 = __ldg(&s0[i0.x >> 1]);
            float2 B0 = __ldg(&s0[i0.y >> 1]);
            float2 T1 = __ldg(&s1[i1.x >> 1]);
            float2 B1 = __ldg(&s1[i1.y >> 1]);
            float v0 = g0.x*T0.x + g0.y*T0.y + g0.z*B0.x + g0.w*B0.y;
            float v1 = g1.x*T1.x + g1.y*T1.y + g1.z*B1.x + g1.w*B1.y;
            u32 hi01; CVT_BF16X2(hi01, v1, v0);
            float fh0 = __uint_as_float(hi01 << 16);
            float fh1 = __uint_as_float(hi01 & 0xFFFF0000u);
            u32 lo01; CVT_BF16X2(lo01, v1 - fh1, v0 - fh0);
            smp[cc*36 + pxw] = hi01;
            smp[64*36 + cc*36 + pxw] = lo01;
        }
        __syncthreads();

        #pragma unroll
        for (int kk = 0; kk < 4; kk++) {
            int ks = n*4 + kk;
            u32 a0[2][4];
            {
                const uint4* ap = (const uint4*)(g_dwf + (((size_t)ks*8 + wm*2)*32 + lane)*4);
                uint4 f0 = ap[0];
                uint4 f1 = ap[32];
                a0[0][0]=f0.x; a0[0][1]=f0.y; a0[0][2]=f0.z; a0[0][3]=f0.w;
                a0[1][0]=f1.x; a0[1][1]=f1.y; a0[1][2]=f1.z; a0[1][3]=f1.w;
            }
            int nsplits = is_wh ? 2 : 1;
            for (int sp = 0; sp < nsplits; sp++) {
                u32 bf[4][2];
                u32 base = sb_smp + sp*9216 + (kk*16 + lm_k)*144;
                #pragma unroll
                for (int li = 0; li < 2; li++) {
                    int nn = nw*32 + li*16 + lm_noff;
                    u32 r0,r1,r2,r3;
                    LDMATRIX_X4_TRANS(r0,r1,r2,r3, base + nn*2);
                    bf[2*li][0]=r0; bf[2*li][1]=r1; bf[2*li+1][0]=r2; bf[2*li+1][1]=r3;
                }
                #pragma unroll
                for (int mi = 0; mi < 2; mi++)
                    #pragma unroll
                    for (int ni = 0; ni < 4; ni++)
                        MMA_BF16(acc[mi][ni][0],acc[mi][ni][1],acc[mi][ni][2],acc[mi][ni][3],
                                 a0[mi][0],a0[mi][1],a0[mi][2],a0[mi][3],
                                 bf[ni][0],bf[ni][1]);
            }
        }
        __syncthreads();
    }

    float* epi = (float*)smp;
    if (!is_wh) {
        int pair = nw*2 + (wm - 2);
        #pragma unroll
        for (int mi = 0; mi < 2; mi++)
            #pragma unroll
            for (int ni = 0; ni < 4; ni++)
                *(float4*)&epi[pair*1024 + (mi*4+ni)*128 + lane*4] = *(float4*)acc[mi][ni];
    }
    __syncthreads();
    if (is_wh) {
        int pair = nw*2 + wm;
        #pragma unroll
        for (int mi = 0; mi < 2; mi++) {
            #pragma unroll
            for (int ni = 0; ni < 4; ni++) {
                float4 part = *(float4*)&epi[pair*1024 + (mi*4+ni)*128 + lane*4];
                int oc = wm*32 + mi*16 + (lane>>2);
                int px = nw*32 + ni*8 + (lane&3)*2;
                float bb0 = db[oc];
                float bb8 = db[oc + 8];
                float v0 = acc[mi][ni][0] + part.x + bb0;
                float v1 = acc[mi][ni][1] + part.y + bb0;
                float v2 = acc[mi][ni][2] + part.z + bb8;
                float v3 = acc[mi][ni][3] + part.w + bb8;
                int wpair = (w0 + px) >> 1;
                size_t base0 = ((size_t)(b*256) + br*64 + oc)*8192 + (size_t)h*64 + wpair;
                size_t base8 = base0 + (size_t)8*8192;
                u32 hi01; CVT_BF16X2(hi01, v1, v0);
                float fh0 = __uint_as_float(hi01 << 16);
                float fh1 = __uint_as_float(hi01 & 0xFFFF0000u);
                u32 lo01; CVT_BF16X2(lo01, v1 - fh1, v0 - fh0);
                g_fs[base0] = hi01;
                g_fs[(size_t)4*256*8192 + base0] = lo01;
                u32 hi23; CVT_BF16X2(hi23, v3, v2);
                float fh2 = __uint_as_float(hi23 << 16);
                float fh3 = __uint_as_float(hi23 & 0xFFFF0000u);
                u32 lo23; CVT_BF16X2(lo23, v3 - fh3, v2 - fh2);
                g_fs[base8] = hi23;
                g_fs[(size_t)4*256*8192 + base8] = lo23;
            }
        }
    }
}

// ================= final 1x1 via MMA (R9 proven form) =================
__global__ void __launch_bounds__(256,2) final_kernel(const float* __restrict__ cb,
                                                      float* __restrict__ out)
{
    __shared__ __align__(16) char sraw[32768];
    u32 sb = smem_to_u32(sraw);

    int tid = threadIdx.x, wid = tid>>5, lane = tid&31;
    int wm = wid & 3, nw = wid >> 2;
    int pt = blockIdx.x, b = blockIdx.y;
    int p0w = pt*64;
    bool is_wh = (wm < 2);

    float acc[2][8][4];
    #pragma unroll
    for (int mi = 0; mi < 2; mi++)
        #pragma unroll
        for (int ni = 0; ni < 8; ni++)
            #pragma unroll
            for (int r = 0; r < 4; r++) acc[mi][ni][r] = 0.f;

    int lm_mat = lane >> 3, lm_row = lane & 7;
    int lm_k = (lm_mat & 1)*8 + lm_row;
    int lm_noff = (lm_mat >> 1)*8;

    auto loadB = [&](int ks, int buf) {
        char* dst = sraw + buf*8704;
        #pragma unroll
        for (int i = 0; i < 8; i++) {
            int idx = tid + 256*i;
            int split = idx >> 10; int rem = idx & 1023;
            int kr = rem >> 6; int j = rem & 63;
            const u32* p = g_fs + ((size_t)(split*4 + b)*256 + ks*16 + kr)*8192 + p0w + j;
            u32 v = __ldg(p);
            *(u32*)(dst + split*4352 + kr*272 + j*4) = v;
        }
    };

    loadB(0, 0);
    __syncthreads();

    for (int ks = 0; ks < 16; ks++) {
        int buf = ks & 1;
        if (ks + 1 < 16) loadB(ks+1, buf^1);

        u32 a0[2][4];
        {
            const uint4* ap = (const uint4*)(g_cwf + (((size_t)ks*8 + wm*2)*32 + lane)*4);
            uint4 f0 = ap[0];
            uint4 f1 = ap[32];
            a0[0][0]=f0.x; a0[0][1]=f0.y; a0[0][2]=f0.z; a0[0][3]=f0.w;
            a0[1][0]=f1.x; a0[1][1]=f1.y; a0[1][2]=f1.z; a0[1][3]=f1.w;
        }

        int nsplits = is_wh ? 2 : 1;
        for (int sp = 0; sp < nsplits; sp++) {
            u32 bf[8][2];
            u32 base = sb + buf*8704 + sp*4352 + lm_k*272;
            #pragma unroll
            for (int li = 0; li < 4; li++) {
                int n = nw*64 + li*16 + lm_noff;
                u32 r0,r1,r2,r3;
                LDMATRIX_X4_TRANS(r0,r1,r2,r3, base + n*2);
                bf[2*li][0]=r0; bf[2*li][1]=r1; bf[2*li+1][0]=r2; bf[2*li+1][1]=r3;
            }
            #pragma unroll
            for (int mi = 0; mi < 2; mi++)
                #pragma unroll
                for (int ni = 0; ni < 8; ni++)
                    MMA_BF16(acc[mi][ni][0],acc[mi][ni][1],acc[mi][ni][2],acc[mi][ni][3],
                             a0[mi][0],a0[mi][1],a0[mi][2],a0[mi][3],
                             bf[ni][0],bf[ni][1]);
        }
        __syncthreads();
    }

    float* epi = (float*)sraw;
    if (!is_wh) {
        int pair = nw*2 + (wm - 2);
        #pragma unroll
        for (int mi = 0; mi < 2; mi++)
            #pragma unroll
            for (int ni = 0; ni < 8; ni++)
                *(float4*)&epi[pair*2048 + (mi*8+ni)*128 + lane*4] = *(float4*)acc[mi][ni];
    }
    __syncthreads();
    if (is_wh) {
        int pair = nw*2 + wm;
        #pragma unroll
        for (int mi = 0; mi < 2; mi++) {
            #pragma unroll
            for (int ni = 0; ni < 8; ni++) {
                float4 part = *(float4*)&epi[pair*2048 + (mi*8+ni)*128 + lane*4];
                int oc = wm*32 + mi*16 + (lane>>2);
                int px = nw*64 + ni*8 + (lane&3)*2;
                float bb0 = cb[oc];
                float bb8 = cb[oc + 8];
                float2 o0, o8;
                o0.x = fmaxf(acc[mi][ni][0] + part.x + bb0, 0.f);
                o0.y = fmaxf(acc[mi][ni][1] + part.y + bb0, 0.f);
                o8.x = fmaxf(acc[mi][ni][2] + part.z + bb8, 0.f);
                o8.y = fmaxf(acc[mi][ni][3] + part.w + bb8, 0.f);
                float* q0 = out + ((size_t)(b*64 + oc))*HW + p0w*2 + px;
                float* q8 = q0 + (size_t)8*HW;
                *(float2*)q0 = o0;
                *(float2*)q8 = o8;
            }
        }
    }
}

// ================= launch =================
extern "C" void kernel_launch(void* const* d_in, const int* in_sizes, int n_in,
                              void* d_out, int out_size)
{
    const float* x   = (const float*)d_in[0];
    const float* w1  = (const float*)d_in[1];
    const float* b1  = (const float*)d_in[2];
    const float* w2  = (const float*)d_in[3];
    const float* b2  = (const float*)d_in[4];
    const float* w3  = (const float*)d_in[5];
    const float* b3  = (const float*)d_in[6];
    const float* w4  = (const float*)d_in[7];
    const float* b4  = (const float*)d_in[8];
    const float* p_w = (const float*)d_in[9];
    const float* p_b = (const float*)d_in[10];
    const float* dw  = (const float*)d_in[11];
    const float* db  = (const float*)d_in[12];
    const float* cw  = (const float*)d_in[13];
    const float* cb  = (const float*)d_in[14];
    float* out = (float*)d_out;

    prep_kernel<<<4096, 256>>>(x, w1, w2, w3, w4, p_w, dw, cw, b1, b2, b3, b4);
    bconv_kernel<<<dim3(128, 4, 4), 256>>>();
    ypair_kernel<<<8840, 256>>>();
    offconv_kernel<<<dim3(128, 16), 256>>>(p_b);
    deform_kernel<<<dim3(2, 128, 16), 256>>>(db);
    final_kernel<<<dim3(128, 4), 256>>>(cb, out);
}

// round 15
// speedup vs baseline: 1.1270x; 1.1270x over previous
#include <cuda_runtime.h>
#include <cuda_bf16.h>
#include <cstdint>

#define BB 4
#define CIN 128
#define CO 64
#define HH 128
#define WW 128
#define HW (HH*WW)

#define PW 136
#define PH 130
#define PPLANE (PH*PW)

#define PLANE_WW 80
#define PLANE_RR 142
#define PLANE_SZ (PLANE_RR*PLANE_WW)

typedef unsigned long long u64;
typedef unsigned int u32;

__device__ __forceinline__ u32 smem_to_u32(const void* p) {
    u32 a; asm("{ .reg .u64 t; cvta.to.shared.u64 t, %1; cvt.u32.u64 %0, t; }" : "=r"(a) : "l"(p));
    return a;
}

#define MMA_BF16(d0,d1,d2,d3,a0,a1,a2,a3,b0,b1) \
    asm volatile("mma.sync.aligned.m16n8k16.row.col.f32.bf16.bf16.f32 " \
        "{%0,%1,%2,%3},{%4,%5,%6,%7},{%8,%9},{%0,%1,%2,%3};" \
        : "+f"(d0),"+f"(d1),"+f"(d2),"+f"(d3) \
        : "r"(a0),"r"(a1),"r"(a2),"r"(a3),"r"(b0),"r"(b1))

#define LDMATRIX_X4_TRANS(r0,r1,r2,r3,addr) \
    asm volatile("ldmatrix.sync.aligned.m8n8.x4.trans.shared.b16 {%0,%1,%2,%3},[%4];" \
        : "=r"(r0),"=r"(r1),"=r"(r2),"=r"(r3) : "r"(addr))

#define CVT_BF16X2(res, hi_f, lo_f) \
    asm("cvt.rn.bf16x2.f32 %0, %1, %2;" : "=r"(res) : "f"(hi_f), "f"(lo_f))

// ================= scratch =================
__device__ u32   g_xs [2*2*4*128*PLANE_SZ];
__device__ u32   g_wfA[4*72*8*32*4];
__device__ u32   g_dwf[36*8*32*4];
__device__ u32   g_pwf[36*4*32*4];
__device__ u32   g_cwf[16*8*32*4];
__device__ float g_bias[4*64];
__device__ float g_yp [16*64*PPLANE];
__device__ float g_off[16*18*HW];
__device__ u32   g_fs [2*4*256*8192];

// ================= prep (merged) =================
__global__ void prep_kernel(const float* __restrict__ x,
                            const float* __restrict__ w1, const float* __restrict__ w2,
                            const float* __restrict__ w3, const float* __restrict__ w4,
                            const float* __restrict__ pw, const float* __restrict__ dwp,
                            const float* __restrict__ cwp,
                            const float* __restrict__ b1, const float* __restrict__ b2,
                            const float* __restrict__ b3, const float* __restrict__ b4)
{
    int tid = blockIdx.x*blockDim.x + threadIdx.x;
    int nt  = gridDim.x*blockDim.x;
    const float* wb[4] = {w1,w2,w3,w4};
    const float* bbv[4] = {b1,b2,b3,b4};

    for (int i = tid; i < 4*72*8*32*4; i += nt) {
        int br = i / 73728; int r2 = i % 73728;
        int ks = r2 >> 10;  int r3 = r2 & 1023;
        int mb = r3 >> 7;   int lane = (r3 >> 2) & 31; int reg = r3 & 3;
        int row = mb*16 + (lane>>2) + (reg&1)*8;
        int k0  = (lane&3)*2 + (reg>>1)*8;
        int oc = row & 63, split = row >> 6;
        int tap = ks >> 3;
        int ic0 = (ks & 7)*16;
        u32 out = 0;
        #pragma unroll
        for (int e = 0; e < 2; e++) {
            float W = wb[br][oc*1152 + (ic0 + k0 + e)*9 + tap];
            __nv_bfloat16 hi = __float2bfloat16(W);
            __nv_bfloat16 v = split ? __float2bfloat16(W - __bfloat162float(hi)) : hi;
            out |= (u32)__bfloat16_as_ushort(v) << (16*e);
        }
        g_wfA[i] = out;
    }
    for (int i = tid; i < 36*8*32*4; i += nt) {
        int ks = i >> 10; int r3 = i & 1023;
        int mb = r3 >> 7; int lane = (r3 >> 2) & 31; int reg = r3 & 3;
        int row = mb*16 + (lane>>2) + (reg&1)*8;
        int k0  = ks*16 + (lane&3)*2 + (reg>>1)*8;
        int oc = row & 63, split = row >> 6;
        u32 out = 0;
        #pragma unroll
        for (int e = 0; e < 2; e++) {
            int k = k0 + e; int c = k & 63; int n = k >> 6;
            float W = dwp[oc*576 + c*9 + n];
            __nv_bfloat16 hi = __float2bfloat16(W);
            __nv_bfloat16 v = split ? __float2bfloat16(W - __bfloat162float(hi)) : hi;
            out |= (u32)__bfloat16_as_ushort(v) << (16*e);
        }
        g_dwf[i] = out;
    }
    for (int i = tid; i < 36*4*32*4; i += nt) {
        int ks = i >> 9; int r3 = i & 511;
        int mb = r3 >> 7; int lane = (r3 >> 2) & 31; int reg = r3 & 3;
        int row = mb*16 + (lane>>2) + (reg&1)*8;
        int k0  = (lane&3)*2 + (reg>>1)*8;
        int oc = row & 31, split = row >> 5;
        int tap = ks >> 2;
        int ic0 = (ks & 3)*16;
        u32 out = 0;
        #pragma unroll
        for (int e = 0; e < 2; e++) {
            float W = (oc < 18) ? pw[oc*576 + (ic0 + k0 + e)*9 + tap] : 0.f;
            __nv_bfloat16 hi = __float2bfloat16(W);
            __nv_bfloat16 v = split ? __float2bfloat16(W - __bfloat162float(hi)) : hi;
            out |= (u32)__bfloat16_as_ushort(v) << (16*e);
        }
        g_pwf[i] = out;
    }
    for (int i = tid; i < 16*8*32*4; i += nt) {
        int ks = i >> 10; int r3 = i & 1023;
        int mb = r3 >> 7; int lane = (r3 >> 2) & 31; int reg = r3 & 3;
        int row = mb*16 + (lane>>2) + (reg&1)*8;
        int k0  = ks*16 + (lane&3)*2 + (reg>>1)*8;
        int oc = row & 63, split = row >> 6;
        u32 out = 0;
        #pragma unroll
        for (int e = 0; e < 2; e++) {
            float W = cwp[oc*256 + k0 + e];
            __nv_bfloat16 hi = __float2bfloat16(W);
            __nv_bfloat16 v = split ? __float2bfloat16(W - __bfloat162float(hi)) : hi;
            out |= (u32)__bfloat16_as_ushort(v) << (16*e);
        }
        g_cwf[i] = out;
    }
    for (int i = tid; i < 256; i += nt) g_bias[i] = bbv[i>>6][i&63];
    for (int i = tid; i < 1024*528; i += nt) {
        int p = i/528; int j = i - p*528;
        int r, c;
        if (j < 136)      { r = 0;       c = j; }
        else if (j < 272) { r = 129;     c = j - 136; }
        else if (j < 400) { r = j - 271; c = 3; }
        else              { r = j - 399; c = 132; }
        g_yp[(size_t)p*PPLANE + r*PW + c] = 0.f;
    }
    {
        size_t total = (size_t)2*4*128*PLANE_SZ;
        for (size_t i = tid; i < total; i += nt) {
            int wd = (int)(i % PLANE_WW); size_t t = i / PLANE_WW;
            int rr = (int)(t % PLANE_RR); t /= PLANE_RR;
            int ic = (int)(t % 128); t /= 128;
            int b  = (int)(t % 4);   t /= 4;
            int phase = (int)t;
            int row = rr - 7;
            int pxa = 2*wd + phase - 8;
            float va = 0.f, vb = 0.f;
            if ((unsigned)row < 128u) {
                const float* xr = x + ((size_t)(b*128+ic)*128 + row)*128;
                if ((unsigned)pxa < 128u)     va = xr[pxa];
                if ((unsigned)(pxa+1) < 128u) vb = xr[pxa+1];
            }
            u32 hi; CVT_BF16X2(hi, vb, va);
            float fhlo = __uint_as_float(hi << 16);
            float fhhi = __uint_as_float(hi & 0xFFFF0000u);
            u32 lo; CVT_BF16X2(lo, vb - fhhi, va - fhlo);
            size_t off = (size_t)rr*PLANE_WW + wd;
            size_t p0 = (size_t)((phase*4 + b)*128 + ic)*PLANE_SZ;
            size_t p1 = (size_t)(((2 + phase)*4 + b)*128 + ic)*PLANE_SZ;
            g_xs[p0 + off] = hi;
            g_xs[p1 + off] = lo;
        }
    }
}

// ================= branch conv (R5 proven form) =================
__global__ void __launch_bounds__(256,2) bconv_kernel()
{
    __shared__ __align__(16) char sraw[33280];
    u32 sb = smem_to_u32(sraw);

    int tid = threadIdx.x, wid = tid>>5, lane = tid&31;
    int wm = wid & 3, nw = wid >> 2;
    int h = blockIdx.x, br = blockIdx.y, b = blockIdx.z;
    int D = 2*br + 1; float scale = (float)D;
    bool is_wh = (wm < 2);

    float acc[2][8][4];
    #pragma unroll
    for (int mi = 0; mi < 2; mi++)
        #pragma unroll
        for (int ni = 0; ni < 8; ni++)
            #pragma unroll
            for (int r = 0; r < 4; r++) acc[mi][ni][r] = 0.f;

    int lm_mat = lane >> 3, lm_row = lane & 7;
    int lm_k = (lm_mat & 1)*8 + lm_row;
    int lm_noff = (lm_mat >> 1)*8;

    auto loadB = [&](int ks, int buf) {
        int tap = ks >> 3, icc = ks & 7;
        int ky = tap/3 - 1, kx = tap - (tap/3)*3 - 1;
        int s = kx*D;
        int phase = (s + 8) & 1;
        int wd0 = (s + 8 - phase) >> 1;
        int srow = h + ky*D + 7;
        char* dst = sraw + buf*8704;
        #pragma unroll
        for (int i = 0; i < 8; i++) {
            int idx = tid + 256*i;
            int split = idx >> 10; int rem = idx & 1023;
            int ic = rem >> 6; int j = rem & 63;
            const u32* p = g_xs + ((size_t)((split*2+phase)*4 + b)*128 + icc*16 + ic)*PLANE_SZ
                         + (size_t)srow*PLANE_WW + wd0 + j;
            u32 v = __ldg(p);
            *(u32*)(dst + split*4352 + ic*272 + j*4) = v;
        }
    };

    loadB(0, 0);
    __syncthreads();

    for (int ks = 0; ks < 72; ks++) {
        int buf = ks & 1;
        if (ks + 1 < 72) loadB(ks+1, buf^1);

        u32 a0[2][4];
        {
            const uint4* ap = (const uint4*)(g_wfA + (((size_t)(br*72 + ks)*8 + wm*2)*32 + lane)*4);
            uint4 f0 = ap[0];
            uint4 f1 = ap[32];
            a0[0][0]=f0.x; a0[0][1]=f0.y; a0[0][2]=f0.z; a0[0][3]=f0.w;
            a0[1][0]=f1.x; a0[1][1]=f1.y; a0[1][2]=f1.z; a0[1][3]=f1.w;
        }

        int nsplits = is_wh ? 2 : 1;
        for (int sp = 0; sp < nsplits; sp++) {
            u32 bf[8][2];
            u32 base = sb + buf*8704 + sp*4352 + lm_k*272;
            #pragma unroll
            for (int li = 0; li < 4; li++) {
                int n = nw*64 + li*16 + lm_noff;
                u32 r0,r1,r2,r3;
                LDMATRIX_X4_TRANS(r0,r1,r2,r3, base + n*2);
                bf[2*li][0]=r0; bf[2*li][1]=r1; bf[2*li+1][0]=r2; bf[2*li+1][1]=r3;
            }
            #pragma unroll
            for (int mi = 0; mi < 2; mi++)
                #pragma unroll
                for (int ni = 0; ni < 8; ni++)
                    MMA_BF16(acc[mi][ni][0],acc[mi][ni][1],acc[mi][ni][2],acc[mi][ni][3],
                             a0[mi][0],a0[mi][1],a0[mi][2],a0[mi][3],
                             bf[ni][0],bf[ni][1]);
        }
        __syncthreads();
    }

    float* epi = (float*)sraw;
    if (!is_wh) {
        int pair = nw*2 + (wm - 2);
        #pragma unroll
        for (int mi = 0; mi < 2; mi++)
            #pragma unroll
            for (int ni = 0; ni < 8; ni++)
                *(float4*)&epi[pair*2048 + (mi*8+ni)*128 + lane*4] = *(float4*)acc[mi][ni];
    }
    __syncthreads();
    if (is_wh) {
        int pair = nw*2 + wm;
        int bi = br*4 + b;
        #pragma unroll
        for (int mi = 0; mi < 2; mi++) {
            #pragma unroll
            for (int ni = 0; ni < 8; ni++) {
                float4 part = *(float4*)&epi[pair*2048 + (mi*8+ni)*128 + lane*4];
                int oc = wm*32 + mi*16 + (lane>>2);
                int px = nw*64 + ni*8 + (lane&3)*2;
                float bb0 = g_bias[br*64 + oc];
                float bb8 = g_bias[br*64 + oc + 8];
                float* p0 = g_yp + ((size_t)(bi*64 + oc))*PPLANE + (size_t)(h+1)*PW + px + 4;
                float* p8 = p0 + (size_t)8*PPLANE;
                float2 o0, o8;
                o0.x = (acc[mi][ni][0] + part.x + bb0)*scale;
                o0.y = (acc[mi][ni][1] + part.y + bb0)*scale;
                o8.x = (acc[mi][ni][2] + part.z + bb8)*scale;
                o8.y = (acc[mi][ni][3] + part.w + bb8)*scale;
                *(float2*)p0 = o0;
                *(float2*)p8 = o8;
            }
        }
    }
}

// ================= offset conv via MMA (R9 proven 2-split form) =================
__global__ void __launch_bounds__(256,3) offconv_kernel(const float* __restrict__ pb)
{
    __shared__ __align__(16) char sraw[17408];
    u32 sb = smem_to_u32(sraw);

    int tid = threadIdx.x, wid = tid>>5, lane = tid&31;
    int wm = wid & 3, nw = wid >> 2;
    int h = blockIdx.x, bi = blockIdx.y;
    bool is_wh = (wm < 2);

    float acc[8][4];
    #pragma unroll
    for (int ni = 0; ni < 8; ni++)
        #pragma unroll
        for (int r = 0; r < 4; r++) acc[ni][r] = 0.f;

    int lm_mat = lane >> 3, lm_row = lane & 7;
    int lm_k = (lm_mat & 1)*8 + lm_row;
    int lm_noff = (lm_mat >> 1)*8;

    const float* ypb = g_yp + (size_t)(bi*64)*PPLANE;

    auto loadB = [&](int ks, int buf) {
        int tap = ks >> 2, icc = ks & 3;
        int ky = tap/3 - 1, kx = tap - (tap/3)*3 - 1;
        int srow = h + ky + 1;
        char* dst = sraw + buf*8704;
        #pragma unroll
        for (int i = 0; i < 4; i++) {
            int idx = tid + 256*i;
            int ic = idx >> 6; int j = idx & 63;
            const float* rp = ypb + (size_t)(icc*16 + ic)*PPLANE
                            + (size_t)srow*PW + 2*j + kx + 4;
            float f0 = rp[0], f1 = rp[1];
            u32 hi; CVT_BF16X2(hi, f1, f0);
            float fh0 = __uint_as_float(hi << 16);
            float fh1 = __uint_as_float(hi & 0xFFFF0000u);
            u32 lo; CVT_BF16X2(lo, f1 - fh1, f0 - fh0);
            *(u32*)(dst + ic*272 + j*4) = hi;
            *(u32*)(dst + 4352 + ic*272 + j*4) = lo;
        }
    };

    loadB(0, 0);
    __syncthreads();

    for (int ks = 0; ks < 36; ks++) {
        int buf = ks & 1;
        if (ks + 1 < 36) loadB(ks+1, buf^1);

        u32 a0[4];
        {
            const uint4* ap = (const uint4*)(g_pwf + (((size_t)ks*4 + wm)*32 + lane)*4);
            uint4 f0 = ap[0];
            a0[0]=f0.x; a0[1]=f0.y; a0[2]=f0.z; a0[3]=f0.w;
        }

        int nsplits = is_wh ? 2 : 1;
        for (int sp = 0; sp < nsplits; sp++) {
            u32 bf[8][2];
            u32 base = sb + buf*8704 + sp*4352 + lm_k*272;
            #pragma unroll
            for (int li = 0; li < 4; li++) {
                int n = nw*64 + li*16 + lm_noff;
                u32 r0,r1,r2,r3;
                LDMATRIX_X4_TRANS(r0,r1,r2,r3, base + n*2);
                bf[2*li][0]=r0; bf[2*li][1]=r1; bf[2*li+1][0]=r2; bf[2*li+1][1]=r3;
            }
            #pragma unroll
            for (int ni = 0; ni < 8; ni++)
                MMA_BF16(acc[ni][0],acc[ni][1],acc[ni][2],acc[ni][3],
                         a0[0],a0[1],a0[2],a0[3],
                         bf[ni][0],bf[ni][1]);
        }
        __syncthreads();
    }

    float* epi = (float*)sraw;
    if (!is_wh) {
        int pair = nw*2 + (wm - 2);
        #pragma unroll
        for (int ni = 0; ni < 8; ni++)
            *(float4*)&epi[pair*1024 + ni*128 + lane*4] = *(float4*)acc[ni];
    }
    __syncthreads();
    if (is_wh) {
        int pair = nw*2 + wm;
        #pragma unroll
        for (int ni = 0; ni < 8; ni++) {
            float4 part = *(float4*)&epi[pair*1024 + ni*128 + lane*4];
            int oc = wm*16 + (lane>>2);
            int px = nw*64 + ni*8 + (lane&3)*2;
            if (oc < 18) {
                float bb = pb[oc];
                float2 o;
                o.x = acc[ni][0] + part.x + bb;
                o.y = acc[ni][1] + part.y + bb;
                *(float2*)&g_off[((size_t)(bi*18 + oc))*HW + h*WW + px] = o;
            }
            int oc8 = oc + 8;
            if (oc8 < 18) {
                float bb = pb[oc8];
                float2 o;
                o.x = acc[ni][2] + part.z + bb;
                o.y = acc[ni][3] + part.w + bb;
                *(float2*)&g_off[((size_t)(bi*18 + oc8))*HW + h*WW + px] = o;
            }
        }
    }
}

// ================= deform: double-buffered sample tile =================
__global__ void __launch_bounds__(256,3) deform_kernel(const float* __restrict__ db)
{
    __shared__ int2   sidx2[576*2];
    __shared__ __align__(16) float4 sgw[576];
    __shared__ __align__(16) u32 smp[2][2*64*36];   // double-buffered
    u32 sb_smp0 = smem_to_u32(smp[0]);
    u32 sb_smp1 = smem_to_u32(smp[1]);

    int tid = threadIdx.x, wid = tid>>5, lane = tid&31;
    int wm = wid & 3, nw = wid >> 2;
    int w0 = blockIdx.x*64;
    int h  = blockIdx.y;
    int bi = blockIdx.z;
    int br = bi >> 2, b = bi & 3;
    bool is_wh = (wm < 2);

    #pragma unroll 1
    for (int t = tid; t < 576; t += 256) {
        int n = t >> 6, px = t & 63;
        int ny = (n*11) >> 5;
        int nx = n - ny*3;
        int wg = w0 + px;
        const float* offp = g_off + (((size_t)(bi*18 + n))*HH + h)*WW + wg;
        float offy = offp[0];
        float offx = offp[9*HW];
        float py  = (float)(h + 1)  + (float)ny - 1.f + offy;
        float pxx = (float)(wg + 1) + (float)nx - 1.f + offx;
        float fy = floorf(py), fx = floorf(pxx);
        float pyc = fminf(fmaxf(py,  0.f), 129.f);
        float pxc = fminf(fmaxf(pxx, 0.f), 129.f);
        float lty = fminf(fmaxf(fy,       0.f), 129.f);
        float rby = fminf(fmaxf(fy + 1.f, 0.f), 129.f);
        float ltx = fminf(fmaxf(fx,       0.f), 129.f);
        float rbx = fminf(fmaxf(fx + 1.f, 0.f), 129.f);
        float gy1 = 1.f + (lty - pyc), gy2 = 1.f - (rby - pyc);
        float gx1 = 1.f + (ltx - pxc), gx2 = 1.f - (rbx - pxc);
        if (!(fx >= 0.f && fx <= 128.f)) { gx1 = 0.f; gx2 = 0.f; }
        int x0b = min(max((int)fx, 0), 128);
        int y0 = (int)lty, y1 = (int)rby;
        sidx2[t] = make_int2(y0*PW + x0b + 3, y1*PW + x0b + 3);
        sgw[t] = make_float4(gy1*gx1, gy1*gx2, gy2*gx1, gy2*gx2);
    }

    int lm_mat = lane >> 3, lm_row = lane & 7;
    int lm_k = (lm_mat & 1)*8 + lm_row;
    int lm_noff = (lm_mat >> 1)*8;

    float acc[2][4][4];
    #pragma unroll
    for (int mi = 0; mi < 2; mi++)
        #pragma unroll
        for (int ni = 0; ni < 4; ni++)
            #pragma unroll
            for (int r = 0; r < 4; r++) acc[mi][ni][r] = 0.f;

    const float* ypb = g_yp + (size_t)bi*CO*PPLANE;

    auto gather = [&](int n, int buf) {
        u32* dst = smp[buf];
        #pragma unroll 1
        for (int u = tid; u < 2048; u += 256) {
            int cc = u >> 5, pxw = u & 31;
            int t = n*64 + pxw*2;
            const float* bp = ypb + (size_t)cc*PPLANE;
            int2 i0 = sidx2[t];     float4 g0 = sgw[t];
            int2 i1 = sidx2[t+1];   float4 g1 = sgw[t+1];
            float v0 = g0.x*bp[i0.x] + g0.y*bp[i0.x+1] + g0.z*bp[i0.y] + g0.w*bp[i0.y+1];
            float v1 = g1.x*bp[i1.x] + g1.y*bp[i1.x+1] + g1.z*bp[i1.y] + g1.w*bp[i1.y+1];
            u32 hi01; CVT_BF16X2(hi01, v1, v0);
            float fh0 = __uint_as_float(hi01 << 16);
            float fh1 = __uint_as_float(hi01 & 0xFFFF0000u);
            u32 lo01; CVT_BF16X2(lo01, v1 - fh1, v0 - fh0);
            dst[cc*36 + pxw] = hi01;
            dst[64*36 + cc*36 + pxw] = lo01;
        }
    };

    __syncthreads();     // sidx2/sgw ready
    gather(0, 0);
    __syncthreads();

    for (int n = 0; n < 9; n++) {
        int buf = n & 1;
        if (n + 1 < 9) gather(n + 1, buf ^ 1);

        u32 sb_cur = buf ? sb_smp1 : sb_smp0;
        #pragma unroll
        for (int kk = 0; kk < 4; kk++) {
            int ks = n*4 + kk;
            u32 a0[2][4];
            {
                const uint4* ap = (const uint4*)(g_dwf + (((size_t)ks*8 + wm*2)*32 + lane)*4);
                uint4 f0 = ap[0];
                uint4 f1 = ap[32];
                a0[0][0]=f0.x; a0[0][1]=f0.y; a0[0][2]=f0.z; a0[0][3]=f0.w;
                a0[1][0]=f1.x; a0[1][1]=f1.y; a0[1][2]=f1.z; a0[1][3]=f1.w;
            }
            int nsplits = is_wh ? 2 : 1;
            for (int sp = 0; sp < nsplits; sp++) {
                u32 bf[4][2];
                u32 base = sb_cur + sp*9216 + (kk*16 + lm_k)*144;
                #pragma unroll
                for (int li = 0; li < 2; li++) {
                    int nn = nw*32 + li*16 + lm_noff;
                    u32 r0,r1,r2,r3;
                    LDMATRIX_X4_TRANS(r0,r1,r2,r3, base + nn*2);
                    bf[2*li][0]=r0; bf[2*li][1]=r1; bf[2*li+1][0]=r2; bf[2*li+1][1]=r3;
                }
                #pragma unroll
                for (int mi = 0; mi < 2; mi++)
                    #pragma unroll
                    for (int ni = 0; ni < 4; ni++)
                        MMA_BF16(acc[mi][ni][0],acc[mi][ni][1],acc[mi][ni][2],acc[mi][ni][3],
                                 a0[mi][0],a0[mi][1],a0[mi][2],a0[mi][3],
                                 bf[ni][0],bf[ni][1]);
            }
        }
        __syncthreads();
    }

    float* epi = (float*)smp[0];
    if (!is_wh) {
        int pair = nw*2 + (wm - 2);
        #pragma unroll
        for (int mi = 0; mi < 2; mi++)
            #pragma unroll
            for (int ni = 0; ni < 4; ni++)
                *(float4*)&epi[pair*1024 + (mi*4+ni)*128 + lane*4] = *(float4*)acc[mi][ni];
    }
    __syncthreads();
    if (is_wh) {
        int pair = nw*2 + wm;
        #pragma unroll
        for (int mi = 0; mi < 2; mi++) {
            #pragma unroll
            for (int ni = 0; ni < 4; ni++) {
                float4 part = *(float4*)&epi[pair*1024 + (mi*4+ni)*128 + lane*4];
                int oc = wm*32 + mi*16 + (lane>>2);
                int px = nw*32 + ni*8 + (lane&3)*2;
                float bb0 = db[oc];
                float bb8 = db[oc + 8];
                float v0 = acc[mi][ni][0] + part.x + bb0;
                float v1 = acc[mi][ni][1] + part.y + bb0;
                float v2 = acc[mi][ni][2] + part.z + bb8;
                float v3 = acc[mi][ni][3] + part.w + bb8;
                int wpair = (w0 + px) >> 1;
                size_t base0 = ((size_t)(b*256) + br*64 + oc)*8192 + (size_t)h*64 + wpair;
                size_t base8 = base0 + (size_t)8*8192;
                u32 hi01; CVT_BF16X2(hi01, v1, v0);
                float fh0 = __uint_as_float(hi01 << 16);
                float fh1 = __uint_as_float(hi01 & 0xFFFF0000u);
                u32 lo01; CVT_BF16X2(lo01, v1 - fh1, v0 - fh0);
                g_fs[base0] = hi01;
                g_fs[(size_t)4*256*8192 + base0] = lo01;
                u32 hi23; CVT_BF16X2(hi23, v3, v2);
                float fh2 = __uint_as_float(hi23 << 16);
                float fh3 = __uint_as_float(hi23 & 0xFFFF0000u);
                u32 lo23; CVT_BF16X2(lo23, v3 - fh3, v2 - fh2);
                g_fs[base8] = hi23;
                g_fs[(size_t)4*256*8192 + base8] = lo23;
            }
        }
    }
}

// ================= final 1x1 via MMA (R9 proven form) =================
__global__ void __launch_bounds__(256,2) final_kernel(const float* __restrict__ cb,
                                                      float* __restrict__ out)
{
    __shared__ __align__(16) char sraw[32768];
    u32 sb = smem_to_u32(sraw);

    int tid = threadIdx.x, wid = tid>>5, lane = tid&31;
    int wm = wid & 3, nw = wid >> 2;
    int pt = blockIdx.x, b = blockIdx.y;
    int p0w = pt*64;
    bool is_wh = (wm < 2);

    float acc[2][8][4];
    #pragma unroll
    for (int mi = 0; mi < 2; mi++)
        #pragma unroll
        for (int ni = 0; ni < 8; ni++)
            #pragma unroll
            for (int r = 0; r < 4; r++) acc[mi][ni][r] = 0.f;

    int lm_mat = lane >> 3, lm_row = lane & 7;
    int lm_k = (lm_mat & 1)*8 + lm_row;
    int lm_noff = (lm_mat >> 1)*8;

    auto loadB = [&](int ks, int buf) {
        char* dst = sraw + buf*8704;
        #pragma unroll
        for (int i = 0; i < 8; i++) {
            int idx = tid + 256*i;
            int split = idx >> 10; int rem = idx & 1023;
            int kr = rem >> 6; int j = rem & 63;
            const u32* p = g_fs + ((size_t)(split*4 + b)*256 + ks*16 + kr)*8192 + p0w + j;
            u32 v = __ldg(p);
            *(u32*)(dst + split*4352 + kr*272 + j*4) = v;
        }
    };

    loadB(0, 0);
    __syncthreads();

    for (int ks = 0; ks < 16; ks++) {
        int buf = ks & 1;
        if (ks + 1 < 16) loadB(ks+1, buf^1);

        u32 a0[2][4];
        {
            const uint4* ap = (const uint4*)(g_cwf + (((size_t)ks*8 + wm*2)*32 + lane)*4);
            uint4 f0 = ap[0];
            uint4 f1 = ap[32];
            a0[0][0]=f0.x; a0[0][1]=f0.y; a0[0][2]=f0.z; a0[0][3]=f0.w;
            a0[1][0]=f1.x; a0[1][1]=f1.y; a0[1][2]=f1.z; a0[1][3]=f1.w;
        }

        int nsplits = is_wh ? 2 : 1;
        for (int sp = 0; sp < nsplits; sp++) {
            u32 bf[8][2];
            u32 base = sb + buf*8704 + sp*4352 + lm_k*272;
            #pragma unroll
            for (int li = 0; li < 4; li++) {
                int n = nw*64 + li*16 + lm_noff;
                u32 r0,r1,r2,r3;
                LDMATRIX_X4_TRANS(r0,r1,r2,r3, base + n*2);
                bf[2*li][0]=r0; bf[2*li][1]=r1; bf[2*li+1][0]=r2; bf[2*li+1][1]=r3;
            }
            #pragma unroll
            for (int mi = 0; mi < 2; mi++)
                #pragma unroll
                for (int ni = 0; ni < 8; ni++)
                    MMA_BF16(acc[mi][ni][0],acc[mi][ni][1],acc[mi][ni][2],acc[mi][ni][3],
                             a0[mi][0],a0[mi][1],a0[mi][2],a0[mi][3],
                             bf[ni][0],bf[ni][1]);
        }
        __syncthreads();
    }

    float* epi = (float*)sraw;
    if (!is_wh) {
        int pair = nw*2 + (wm - 2);
        #pragma unroll
        for (int mi = 0; mi < 2; mi++)
            #pragma unroll
            for (int ni = 0; ni < 8; ni++)
                *(float4*)&epi[pair*2048 + (mi*8+ni)*128 + lane*4] = *(float4*)acc[mi][ni];
    }
    __syncthreads();
    if (is_wh) {
        int pair = nw*2 + wm;
        #pragma unroll
        for (int mi = 0; mi < 2; mi++) {
            #pragma unroll
            for (int ni = 0; ni < 8; ni++) {
                float4 part = *(float4*)&epi[pair*2048 + (mi*8+ni)*128 + lane*4];
                int oc = wm*32 + mi*16 + (lane>>2);
                int px = nw*64 + ni*8 + (lane&3)*2;
                float bb0 = cb[oc];
                float bb8 = cb[oc + 8];
                float2 o0, o8;
                o0.x = fmaxf(acc[mi][ni][0] + part.x + bb0, 0.f);
                o0.y = fmaxf(acc[mi][ni][1] + part.y + bb0, 0.f);
                o8.x = fmaxf(acc[mi][ni][2] + part.z + bb8, 0.f);
                o8.y = fmaxf(acc[mi][ni][3] + part.w + bb8, 0.f);
                float* q0 = out + ((size_t)(b*64 + oc))*HW + p0w*2 + px;
                float* q8 = q0 + (size_t)8*HW;
                *(float2*)q0 = o0;
                *(float2*)q8 = o8;
            }
        }
    }
}

// ================= launch =================
extern "C" void kernel_launch(void* const* d_in, const int* in_sizes, int n_in,
                              void* d_out, int out_size)
{
    const float* x   = (const float*)d_in[0];
    const float* w1  = (const float*)d_in[1];
    const float* b1  = (const float*)d_in[2];
    const float* w2  = (const float*)d_in[3];
    const float* b2  = (const float*)d_in[4];
    const float* w3  = (const float*)d_in[5];
    const float* b3  = (const float*)d_in[6];
    const float* w4  = (const float*)d_in[7];
    const float* b4  = (const float*)d_in[8];
    const float* p_w = (const float*)d_in[9];
    const float* p_b = (const float*)d_in[10];
    const float* dw  = (const float*)d_in[11];
    const float* db  = (const float*)d_in[12];
    const float* cw  = (const float*)d_in[13];
    const float* cb  = (const float*)d_in[14];
    float* out = (float*)d_out;

    prep_kernel<<<4096, 256>>>(x, w1, w2, w3, w4, p_w, dw, cw, b1, b2, b3, b4);
    bconv_kernel<<<dim3(128, 4, 4), 256>>>();
    offconv_kernel<<<dim3(128, 16), 256>>>(p_b);
    deform_kernel<<<dim3(2, 128, 16), 256>>>(db);
    final_kernel<<<dim3(128, 4), 256>>>(cb, out);
}

// round 16
// speedup vs baseline: 1.2584x; 1.1166x over previous
#include <cuda_runtime.h>
#include <cuda_bf16.h>
#include <cstdint>

#define BB 4
#define CIN 128
#define CO 64
#define HH 128
#define WW 128
#define HW (HH*WW)

#define PW 136
#define PH 130
#define PPLANE (PH*PW)

#define CW 130
#define CPLANE (PH*CW*64)   // NHWC plane per bi (floats)

#define PLANE_WW 80
#define PLANE_RR 142
#define PLANE_SZ (PLANE_RR*PLANE_WW)

typedef unsigned long long u64;
typedef unsigned int u32;

__device__ __forceinline__ u32 smem_to_u32(const void* p) {
    u32 a; asm("{ .reg .u64 t; cvta.to.shared.u64 t, %1; cvt.u32.u64 %0, t; }" : "=r"(a) : "l"(p));
    return a;
}

#define MMA_BF16(d0,d1,d2,d3,a0,a1,a2,a3,b0,b1) \
    asm volatile("mma.sync.aligned.m16n8k16.row.col.f32.bf16.bf16.f32 " \
        "{%0,%1,%2,%3},{%4,%5,%6,%7},{%8,%9},{%0,%1,%2,%3};" \
        : "+f"(d0),"+f"(d1),"+f"(d2),"+f"(d3) \
        : "r"(a0),"r"(a1),"r"(a2),"r"(a3),"r"(b0),"r"(b1))

#define LDMATRIX_X4_TRANS(r0,r1,r2,r3,addr) \
    asm volatile("ldmatrix.sync.aligned.m8n8.x4.trans.shared.b16 {%0,%1,%2,%3},[%4];" \
        : "=r"(r0),"=r"(r1),"=r"(r2),"=r"(r3) : "r"(addr))

#define CVT_BF16X2(res, hi_f, lo_f) \
    asm("cvt.rn.bf16x2.f32 %0, %1, %2;" : "=r"(res) : "f"(hi_f), "f"(lo_f))

// ================= scratch =================
__device__ u32   g_xs [2*2*4*128*PLANE_SZ];
__device__ u32   g_wfA[4*72*8*32*4];
__device__ u32   g_dwf[36*8*32*4];
__device__ u32   g_pwf[36*4*32*4];
__device__ u32   g_cwf[16*8*32*4];
__device__ float g_bias[4*64];
__device__ float g_yp [16*64*PPLANE];
__device__ float g_ypc[16*CPLANE];       // NHWC: [bi][row][col'][ch]
__device__ float g_off[16*18*HW];
__device__ u32   g_fs [2*4*256*8192];

// ================= prep (merged) =================
__global__ void prep_kernel(const float* __restrict__ x,
                            const float* __restrict__ w1, const float* __restrict__ w2,
                            const float* __restrict__ w3, const float* __restrict__ w4,
                            const float* __restrict__ pw, const float* __restrict__ dwp,
                            const float* __restrict__ cwp,
                            const float* __restrict__ b1, const float* __restrict__ b2,
                            const float* __restrict__ b3, const float* __restrict__ b4)
{
    int tid = blockIdx.x*blockDim.x + threadIdx.x;
    int nt  = gridDim.x*blockDim.x;
    const float* wb[4] = {w1,w2,w3,w4};
    const float* bbv[4] = {b1,b2,b3,b4};

    for (int i = tid; i < 4*72*8*32*4; i += nt) {
        int br = i / 73728; int r2 = i % 73728;
        int ks = r2 >> 10;  int r3 = r2 & 1023;
        int mb = r3 >> 7;   int lane = (r3 >> 2) & 31; int reg = r3 & 3;
        int row = mb*16 + (lane>>2) + (reg&1)*8;
        int k0  = (lane&3)*2 + (reg>>1)*8;
        int oc = row & 63, split = row >> 6;
        int tap = ks >> 3;
        int ic0 = (ks & 7)*16;
        u32 out = 0;
        #pragma unroll
        for (int e = 0; e < 2; e++) {
            float W = wb[br][oc*1152 + (ic0 + k0 + e)*9 + tap];
            __nv_bfloat16 hi = __float2bfloat16(W);
            __nv_bfloat16 v = split ? __float2bfloat16(W - __bfloat162float(hi)) : hi;
            out |= (u32)__bfloat16_as_ushort(v) << (16*e);
        }
        g_wfA[i] = out;
    }
    for (int i = tid; i < 36*8*32*4; i += nt) {
        int ks = i >> 10; int r3 = i & 1023;
        int mb = r3 >> 7; int lane = (r3 >> 2) & 31; int reg = r3 & 3;
        int row = mb*16 + (lane>>2) + (reg&1)*8;
        int k0  = ks*16 + (lane&3)*2 + (reg>>1)*8;
        int oc = row & 63, split = row >> 6;
        u32 out = 0;
        #pragma unroll
        for (int e = 0; e < 2; e++) {
            int k = k0 + e; int c = k & 63; int n = k >> 6;
            float W = dwp[oc*576 + c*9 + n];
            __nv_bfloat16 hi = __float2bfloat16(W);
            __nv_bfloat16 v = split ? __float2bfloat16(W - __bfloat162float(hi)) : hi;
            out |= (u32)__bfloat16_as_ushort(v) << (16*e);
        }
        g_dwf[i] = out;
    }
    for (int i = tid; i < 36*4*32*4; i += nt) {
        int ks = i >> 9; int r3 = i & 511;
        int mb = r3 >> 7; int lane = (r3 >> 2) & 31; int reg = r3 & 3;
        int row = mb*16 + (lane>>2) + (reg&1)*8;
        int k0  = (lane&3)*2 + (reg>>1)*8;
        int oc = row & 31, split = row >> 5;
        int tap = ks >> 2;
        int ic0 = (ks & 3)*16;
        u32 out = 0;
        #pragma unroll
        for (int e = 0; e < 2; e++) {
            float W = (oc < 18) ? pw[oc*576 + (ic0 + k0 + e)*9 + tap] : 0.f;
            __nv_bfloat16 hi = __float2bfloat16(W);
            __nv_bfloat16 v = split ? __float2bfloat16(W - __bfloat162float(hi)) : hi;
            out |= (u32)__bfloat16_as_ushort(v) << (16*e);
        }
        g_pwf[i] = out;
    }
    for (int i = tid; i < 16*8*32*4; i += nt) {
        int ks = i >> 10; int r3 = i & 1023;
        int mb = r3 >> 7; int lane = (r3 >> 2) & 31; int reg = r3 & 3;
        int row = mb*16 + (lane>>2) + (reg&1)*8;
        int k0  = ks*16 + (lane&3)*2 + (reg>>1)*8;
        int oc = row & 63, split = row >> 6;
        u32 out = 0;
        #pragma unroll
        for (int e = 0; e < 2; e++) {
            float W = cwp[oc*256 + k0 + e];
            __nv_bfloat16 hi = __float2bfloat16(W);
            __nv_bfloat16 v = split ? __float2bfloat16(W - __bfloat162float(hi)) : hi;
            out |= (u32)__bfloat16_as_ushort(v) << (16*e);
        }
        g_cwf[i] = out;
    }
    for (int i = tid; i < 256; i += nt) g_bias[i] = bbv[i>>6][i&63];
    for (int i = tid; i < 1024*528; i += nt) {
        int p = i/528; int j = i - p*528;
        int r, c;
        if (j < 136)      { r = 0;       c = j; }
        else if (j < 272) { r = 129;     c = j - 136; }
        else if (j < 400) { r = j - 271; c = 3; }
        else              { r = j - 399; c = 132; }
        g_yp[(size_t)p*PPLANE + r*PW + c] = 0.f;
    }
    {
        size_t total = (size_t)2*4*128*PLANE_SZ;
        for (size_t i = tid; i < total; i += nt) {
            int wd = (int)(i % PLANE_WW); size_t t = i / PLANE_WW;
            int rr = (int)(t % PLANE_RR); t /= PLANE_RR;
            int ic = (int)(t % 128); t /= 128;
            int b  = (int)(t % 4);   t /= 4;
            int phase = (int)t;
            int row = rr - 7;
            int pxa = 2*wd + phase - 8;
            float va = 0.f, vb = 0.f;
            if ((unsigned)row < 128u) {
                const float* xr = x + ((size_t)(b*128+ic)*128 + row)*128;
                if ((unsigned)pxa < 128u)     va = xr[pxa];
                if ((unsigned)(pxa+1) < 128u) vb = xr[pxa+1];
            }
            u32 hi; CVT_BF16X2(hi, vb, va);
            float fhlo = __uint_as_float(hi << 16);
            float fhhi = __uint_as_float(hi & 0xFFFF0000u);
            u32 lo; CVT_BF16X2(lo, vb - fhhi, va - fhlo);
            size_t off = (size_t)rr*PLANE_WW + wd;
            size_t p0 = (size_t)((phase*4 + b)*128 + ic)*PLANE_SZ;
            size_t p1 = (size_t)(((2 + phase)*4 + b)*128 + ic)*PLANE_SZ;
            g_xs[p0 + off] = hi;
            g_xs[p1 + off] = lo;
        }
    }
}

// ================= branch conv (R5 proven form) =================
__global__ void __launch_bounds__(256,2) bconv_kernel()
{
    __shared__ __align__(16) char sraw[33280];
    u32 sb = smem_to_u32(sraw);

    int tid = threadIdx.x, wid = tid>>5, lane = tid&31;
    int wm = wid & 3, nw = wid >> 2;
    int h = blockIdx.x, br = blockIdx.y, b = blockIdx.z;
    int D = 2*br + 1; float scale = (float)D;
    bool is_wh = (wm < 2);

    float acc[2][8][4];
    #pragma unroll
    for (int mi = 0; mi < 2; mi++)
        #pragma unroll
        for (int ni = 0; ni < 8; ni++)
            #pragma unroll
            for (int r = 0; r < 4; r++) acc[mi][ni][r] = 0.f;

    int lm_mat = lane >> 3, lm_row = lane & 7;
    int lm_k = (lm_mat & 1)*8 + lm_row;
    int lm_noff = (lm_mat >> 1)*8;

    auto loadB = [&](int ks, int buf) {
        int tap = ks >> 3, icc = ks & 7;
        int ky = tap/3 - 1, kx = tap - (tap/3)*3 - 1;
        int s = kx*D;
        int phase = (s + 8) & 1;
        int wd0 = (s + 8 - phase) >> 1;
        int srow = h + ky*D + 7;
        char* dst = sraw + buf*8704;
        #pragma unroll
        for (int i = 0; i < 8; i++) {
            int idx = tid + 256*i;
            int split = idx >> 10; int rem = idx & 1023;
            int ic = rem >> 6; int j = rem & 63;
            const u32* p = g_xs + ((size_t)((split*2+phase)*4 + b)*128 + icc*16 + ic)*PLANE_SZ
                         + (size_t)srow*PLANE_WW + wd0 + j;
            u32 v = __ldg(p);
            *(u32*)(dst + split*4352 + ic*272 + j*4) = v;
        }
    };

    loadB(0, 0);
    __syncthreads();

    for (int ks = 0; ks < 72; ks++) {
        int buf = ks & 1;
        if (ks + 1 < 72) loadB(ks+1, buf^1);

        u32 a0[2][4];
        {
            const uint4* ap = (const uint4*)(g_wfA + (((size_t)(br*72 + ks)*8 + wm*2)*32 + lane)*4);
            uint4 f0 = ap[0];
            uint4 f1 = ap[32];
            a0[0][0]=f0.x; a0[0][1]=f0.y; a0[0][2]=f0.z; a0[0][3]=f0.w;
            a0[1][0]=f1.x; a0[1][1]=f1.y; a0[1][2]=f1.z; a0[1][3]=f1.w;
        }

        int nsplits = is_wh ? 2 : 1;
        for (int sp = 0; sp < nsplits; sp++) {
            u32 bf[8][2];
            u32 base = sb + buf*8704 + sp*4352 + lm_k*272;
            #pragma unroll
            for (int li = 0; li < 4; li++) {
                int n = nw*64 + li*16 + lm_noff;
                u32 r0,r1,r2,r3;
                LDMATRIX_X4_TRANS(r0,r1,r2,r3, base + n*2);
                bf[2*li][0]=r0; bf[2*li][1]=r1; bf[2*li+1][0]=r2; bf[2*li+1][1]=r3;
            }
            #pragma unroll
            for (int mi = 0; mi < 2; mi++)
                #pragma unroll
                for (int ni = 0; ni < 8; ni++)
                    MMA_BF16(acc[mi][ni][0],acc[mi][ni][1],acc[mi][ni][2],acc[mi][ni][3],
                             a0[mi][0],a0[mi][1],a0[mi][2],a0[mi][3],
                             bf[ni][0],bf[ni][1]);
        }
        __syncthreads();
    }

    float* epi = (float*)sraw;
    if (!is_wh) {
        int pair = nw*2 + (wm - 2);
        #pragma unroll
        for (int mi = 0; mi < 2; mi++)
            #pragma unroll
            for (int ni = 0; ni < 8; ni++)
                *(float4*)&epi[pair*2048 + (mi*8+ni)*128 + lane*4] = *(float4*)acc[mi][ni];
    }
    __syncthreads();
    if (is_wh) {
        int pair = nw*2 + wm;
        int bi = br*4 + b;
        #pragma unroll
        for (int mi = 0; mi < 2; mi++) {
            #pragma unroll
            for (int ni = 0; ni < 8; ni++) {
                float4 part = *(float4*)&epi[pair*2048 + (mi*8+ni)*128 + lane*4];
                int oc = wm*32 + mi*16 + (lane>>2);
                int px = nw*64 + ni*8 + (lane&3)*2;
                float bb0 = g_bias[br*64 + oc];
                float bb8 = g_bias[br*64 + oc + 8];
                float* p0 = g_yp + ((size_t)(bi*64 + oc))*PPLANE + (size_t)(h+1)*PW + px + 4;
                float* p8 = p0 + (size_t)8*PPLANE;
                float2 o0, o8;
                o0.x = (acc[mi][ni][0] + part.x + bb0)*scale;
                o0.y = (acc[mi][ni][1] + part.y + bb0)*scale;
                o8.x = (acc[mi][ni][2] + part.z + bb8)*scale;
                o8.y = (acc[mi][ni][3] + part.w + bb8)*scale;
                *(float2*)p0 = o0;
                *(float2*)p8 = o8;
            }
        }
    }
}

// ================= ytr: g_yp (CHW padded) -> g_ypc (NHWC) =================
// grid (130 rows, 16 bi), 256 threads
__global__ void ytr_kernel()
{
    __shared__ float s[64*133];
    int tid = threadIdx.x, lane = tid & 31, wid = tid >> 5;
    int row = blockIdx.x, bi = blockIdx.y;

    #pragma unroll
    for (int k = 0; k < 8; k++) {
        int ch = wid + 8*k;
        const float* src = g_yp + ((size_t)(bi*64 + ch))*PPLANE + (size_t)row*PW + 3;
        #pragma unroll
        for (int c = 0; c < 5; c++) {
            int col = lane + c*32;
            if (col < 130) s[ch*133 + col] = src[col];
        }
    }
    __syncthreads();

    float* dst = g_ypc + (size_t)bi*CPLANE + (size_t)row*CW*64;
    for (int i = tid; i < 130*64; i += 256) {
        int col = i >> 6, ch = i & 63;
        dst[i] = s[ch*133 + col];
    }
}

// ================= offset conv via MMA (R9 proven 2-split form) =================
__global__ void __launch_bounds__(256,3) offconv_kernel(const float* __restrict__ pb)
{
    __shared__ __align__(16) char sraw[17408];
    u32 sb = smem_to_u32(sraw);

    int tid = threadIdx.x, wid = tid>>5, lane = tid&31;
    int wm = wid & 3, nw = wid >> 2;
    int h = blockIdx.x, bi = blockIdx.y;
    bool is_wh = (wm < 2);

    float acc[8][4];
    #pragma unroll
    for (int ni = 0; ni < 8; ni++)
        #pragma unroll
        for (int r = 0; r < 4; r++) acc[ni][r] = 0.f;

    int lm_mat = lane >> 3, lm_row = lane & 7;
    int lm_k = (lm_mat & 1)*8 + lm_row;
    int lm_noff = (lm_mat >> 1)*8;

    const float* ypb = g_yp + (size_t)(bi*64)*PPLANE;

    auto loadB = [&](int ks, int buf) {
        int tap = ks >> 2, icc = ks & 3;
        int ky = tap/3 - 1, kx = tap - (tap/3)*3 - 1;
        int srow = h + ky + 1;
        char* dst = sraw + buf*8704;
        #pragma unroll
        for (int i = 0; i < 4; i++) {
            int idx = tid + 256*i;
            int ic = idx >> 6; int j = idx & 63;
            const float* rp = ypb + (size_t)(icc*16 + ic)*PPLANE
                            + (size_t)srow*PW + 2*j + kx + 4;
            float f0 = rp[0], f1 = rp[1];
            u32 hi; CVT_BF16X2(hi, f1, f0);
            float fh0 = __uint_as_float(hi << 16);
            float fh1 = __uint_as_float(hi & 0xFFFF0000u);
            u32 lo; CVT_BF16X2(lo, f1 - fh1, f0 - fh0);
            *(u32*)(dst + ic*272 + j*4) = hi;
            *(u32*)(dst + 4352 + ic*272 + j*4) = lo;
        }
    };

    loadB(0, 0);
    __syncthreads();

    for (int ks = 0; ks < 36; ks++) {
        int buf = ks & 1;
        if (ks + 1 < 36) loadB(ks+1, buf^1);

        u32 a0[4];
        {
            const uint4* ap = (const uint4*)(g_pwf + (((size_t)ks*4 + wm)*32 + lane)*4);
            uint4 f0 = ap[0];
            a0[0]=f0.x; a0[1]=f0.y; a0[2]=f0.z; a0[3]=f0.w;
        }

        int nsplits = is_wh ? 2 : 1;
        for (int sp = 0; sp < nsplits; sp++) {
            u32 bf[8][2];
            u32 base = sb + buf*8704 + sp*4352 + lm_k*272;
            #pragma unroll
            for (int li = 0; li < 4; li++) {
                int n = nw*64 + li*16 + lm_noff;
                u32 r0,r1,r2,r3;
                LDMATRIX_X4_TRANS(r0,r1,r2,r3, base + n*2);
                bf[2*li][0]=r0; bf[2*li][1]=r1; bf[2*li+1][0]=r2; bf[2*li+1][1]=r3;
            }
            #pragma unroll
            for (int ni = 0; ni < 8; ni++)
                MMA_BF16(acc[ni][0],acc[ni][1],acc[ni][2],acc[ni][3],
                         a0[0],a0[1],a0[2],a0[3],
                         bf[ni][0],bf[ni][1]);
        }
        __syncthreads();
    }

    float* epi = (float*)sraw;
    if (!is_wh) {
        int pair = nw*2 + (wm - 2);
        #pragma unroll
        for (int ni = 0; ni < 8; ni++)
            *(float4*)&epi[pair*1024 + ni*128 + lane*4] = *(float4*)acc[ni];
    }
    __syncthreads();
    if (is_wh) {
        int pair = nw*2 + wm;
        #pragma unroll
        for (int ni = 0; ni < 8; ni++) {
            float4 part = *(float4*)&epi[pair*1024 + ni*128 + lane*4];
            int oc = wm*16 + (lane>>2);
            int px = nw*64 + ni*8 + (lane&3)*2;
            if (oc < 18) {
                float bb = pb[oc];
                float2 o;
                o.x = acc[ni][0] + part.x + bb;
                o.y = acc[ni][1] + part.y + bb;
                *(float2*)&g_off[((size_t)(bi*18 + oc))*HW + h*WW + px] = o;
            }
            int oc8 = oc + 8;
            if (oc8 < 18) {
                float bb = pb[oc8];
                float2 o;
                o.x = acc[ni][2] + part.z + bb;
                o.y = acc[ni][3] + part.w + bb;
                *(float2*)&g_off[((size_t)(bi*18 + oc8))*HW + h*WW + px] = o;
            }
        }
    }
}

// ================= deform: NHWC coalesced gather + MMA =================
__global__ void __launch_bounds__(256,3) deform_kernel(const float* __restrict__ db)
{
    __shared__ int2   sidx2[576*2];
    __shared__ __align__(16) float4 sgw[576];
    __shared__ __align__(16) u32 smp[2][2*64*36];
    u32 sb_smp0 = smem_to_u32(smp[0]);
    u32 sb_smp1 = smem_to_u32(smp[1]);

    int tid = threadIdx.x, wid = tid>>5, lane = tid&31;
    int wm = wid & 3, nw = wid >> 2;
    int w0 = blockIdx.x*64;
    int h  = blockIdx.y;
    int bi = blockIdx.z;
    int br = bi >> 2, b = bi & 3;
    bool is_wh = (wm < 2);

    #pragma unroll 1
    for (int t = tid; t < 576; t += 256) {
        int n = t >> 6, px = t & 63;
        int ny = (n*11) >> 5;
        int nx = n - ny*3;
        int wg = w0 + px;
        const float* offp = g_off + (((size_t)(bi*18 + n))*HH + h)*WW + wg;
        float offy = offp[0];
        float offx = offp[9*HW];
        float py  = (float)(h + 1)  + (float)ny - 1.f + offy;
        float pxx = (float)(wg + 1) + (float)nx - 1.f + offx;
        float fy = floorf(py), fx = floorf(pxx);
        float pyc = fminf(fmaxf(py,  0.f), 129.f);
        float pxc = fminf(fmaxf(pxx, 0.f), 129.f);
        float lty = fminf(fmaxf(fy,       0.f), 129.f);
        float rby = fminf(fmaxf(fy + 1.f, 0.f), 129.f);
        float ltx = fminf(fmaxf(fx,       0.f), 129.f);
        float rbx = fminf(fmaxf(fx + 1.f, 0.f), 129.f);
        float gy1 = 1.f + (lty - pyc), gy2 = 1.f - (rby - pyc);
        float gx1 = 1.f + (ltx - pxc), gx2 = 1.f - (rbx - pxc);
        if (!(fx >= 0.f && fx <= 128.f)) { gx1 = 0.f; gx2 = 0.f; }
        int x0b = min(max((int)fx, 0), 128);
        int y0 = (int)lty, y1 = (int)rby;
        // NHWC indices: (y*CW + x0b)*64 ; col' = x0b (col 3 in g_yp == col' 0)
        sidx2[t] = make_int2((y0*CW + x0b)*64, (y1*CW + x0b)*64);
        sgw[t] = make_float4(gy1*gx1, gy1*gx2, gy2*gx1, gy2*gx2);
    }

    int lm_mat = lane >> 3, lm_row = lane & 7;
    int lm_k = (lm_mat & 1)*8 + lm_row;
    int lm_noff = (lm_mat >> 1)*8;

    float acc[2][4][4];
    #pragma unroll
    for (int mi = 0; mi < 2; mi++)
        #pragma unroll
        for (int ni = 0; ni < 4; ni++)
            #pragma unroll
            for (int r = 0; r < 4; r++) acc[mi][ni][r] = 0.f;

    const float* ypc = g_ypc + (size_t)bi*CPLANE;

    // lane = channel-within-halfwarp group: u = tid + 256*i; ch = u&63 (const per thread),
    // pxw = u>>6 (varies) -> uniform per warp -> coalesced channel loads.
    auto gather = [&](int n, int buf) {
        u32* dst = smp[buf];
        int ch = tid & 63;
        #pragma unroll 1
        for (int u = tid; u < 2048; u += 256) {
            int pxw = u >> 6;
            int t = n*64 + pxw*2;
            int2 i0 = sidx2[t];     float4 g0 = sgw[t];
            int2 i1 = sidx2[t+1];   float4 g1 = sgw[t+1];
            float v0 = g0.x*ypc[i0.x + ch] + g0.y*ypc[i0.x + 64 + ch]
                     + g0.z*ypc[i0.y + ch] + g0.w*ypc[i0.y + 64 + ch];
            float v1 = g1.x*ypc[i1.x + ch] + g1.y*ypc[i1.x + 64 + ch]
                     + g1.z*ypc[i1.y + ch] + g1.w*ypc[i1.y + 64 + ch];
            u32 hi01; CVT_BF16X2(hi01, v1, v0);
            float fh0 = __uint_as_float(hi01 << 16);
            float fh1 = __uint_as_float(hi01 & 0xFFFF0000u);
            u32 lo01; CVT_BF16X2(lo01, v1 - fh1, v0 - fh0);
            dst[ch*36 + pxw] = hi01;
            dst[64*36 + ch*36 + pxw] = lo01;
        }
    };

    __syncthreads();
    gather(0, 0);
    __syncthreads();

    for (int n = 0; n < 9; n++) {
        int buf = n & 1;
        if (n + 1 < 9) gather(n + 1, buf ^ 1);

        u32 sb_cur = buf ? sb_smp1 : sb_smp0;
        #pragma unroll
        for (int kk = 0; kk < 4; kk++) {
            int ks = n*4 + kk;
            u32 a0[2][4];
            {
                const uint4* ap = (const uint4*)(g_dwf + (((size_t)ks*8 + wm*2)*32 + lane)*4);
                uint4 f0 = ap[0];
                uint4 f1 = ap[32];
                a0[0][0]=f0.x; a0[0][1]=f0.y; a0[0][2]=f0.z; a0[0][3]=f0.w;
                a0[1][0]=f1.x; a0[1][1]=f1.y; a0[1][2]=f1.z; a0[1][3]=f1.w;
            }
            int nsplits = is_wh ? 2 : 1;
            for (int sp = 0; sp < nsplits; sp++) {
                u32 bf[4][2];
                u32 base = sb_cur + sp*9216 + (kk*16 + lm_k)*144;
                #pragma unroll
                for (int li = 0; li < 2; li++) {
                    int nn = nw*32 + li*16 + lm_noff;
                    u32 r0,r1,r2,r3;
                    LDMATRIX_X4_TRANS(r0,r1,r2,r3, base + nn*2);
                    bf[2*li][0]=r0; bf[2*li][1]=r1; bf[2*li+1][0]=r2; bf[2*li+1][1]=r3;
                }
                #pragma unroll
                for (int mi = 0; mi < 2; mi++)
                    #pragma unroll
                    for (int ni = 0; ni < 4; ni++)
                        MMA_BF16(acc[mi][ni][0],acc[mi][ni][1],acc[mi][ni][2],acc[mi][ni][3],
                                 a0[mi][0],a0[mi][1],a0[mi][2],a0[mi][3],
                                 bf[ni][0],bf[ni][1]);
            }
        }
        __syncthreads();
    }

    float* epi = (float*)smp[0];
    if (!is_wh) {
        int pair = nw*2 + (wm - 2);
        #pragma unroll
        for (int mi = 0; mi < 2; mi++)
            #pragma unroll
            for (int ni = 0; ni < 4; ni++)
                *(float4*)&epi[pair*1024 + (mi*4+ni)*128 + lane*4] = *(float4*)acc[mi][ni];
    }
    __syncthreads();
    if (is_wh) {
        int pair = nw*2 + wm;
        #pragma unroll
        for (int mi = 0; mi < 2; mi++) {
            #pragma unroll
            for (int ni = 0; ni < 4; ni++) {
                float4 part = *(float4*)&epi[pair*1024 + (mi*4+ni)*128 + lane*4];
                int oc = wm*32 + mi*16 + (lane>>2);
                int px = nw*32 + ni*8 + (lane&3)*2;
                float bb0 = db[oc];
                float bb8 = db[oc + 8];
                float v0 = acc[mi][ni][0] + part.x + bb0;
                float v1 = acc[mi][ni][1] + part.y + bb0;
                float v2 = acc[mi][ni][2] + part.z + bb8;
                float v3 = acc[mi][ni][3] + part.w + bb8;
                int wpair = (w0 + px) >> 1;
                size_t base0 = ((size_t)(b*256) + br*64 + oc)*8192 + (size_t)h*64 + wpair;
                size_t base8 = base0 + (size_t)8*8192;
                u32 hi01; CVT_BF16X2(hi01, v1, v0);
                float fh0 = __uint_as_float(hi01 << 16);
                float fh1 = __uint_as_float(hi01 & 0xFFFF0000u);
                u32 lo01; CVT_BF16X2(lo01, v1 - fh1, v0 - fh0);
                g_fs[base0] = hi01;
                g_fs[(size_t)4*256*8192 + base0] = lo01;
                u32 hi23; CVT_BF16X2(hi23, v3, v2);
                float fh2 = __uint_as_float(hi23 << 16);
                float fh3 = __uint_as_float(hi23 & 0xFFFF0000u);
                u32 lo23; CVT_BF16X2(lo23, v3 - fh3, v2 - fh2);
                g_fs[base8] = hi23;
                g_fs[(size_t)4*256*8192 + base8] = lo23;
            }
        }
    }
}

// ================= final 1x1 via MMA (R9 proven form) =================
__global__ void __launch_bounds__(256,2) final_kernel(const float* __restrict__ cb,
                                                      float* __restrict__ out)
{
    __shared__ __align__(16) char sraw[32768];
    u32 sb = smem_to_u32(sraw);

    int tid = threadIdx.x, wid = tid>>5, lane = tid&31;
    int wm = wid & 3, nw = wid >> 2;
    int pt = blockIdx.x, b = blockIdx.y;
    int p0w = pt*64;
    bool is_wh = (wm < 2);

    float acc[2][8][4];
    #pragma unroll
    for (int mi = 0; mi < 2; mi++)
        #pragma unroll
        for (int ni = 0; ni < 8; ni++)
            #pragma unroll
            for (int r = 0; r < 4; r++) acc[mi][ni][r] = 0.f;

    int lm_mat = lane >> 3, lm_row = lane & 7;
    int lm_k = (lm_mat & 1)*8 + lm_row;
    int lm_noff = (lm_mat >> 1)*8;

    auto loadB = [&](int ks, int buf) {
        char* dst = sraw + buf*8704;
        #pragma unroll
        for (int i = 0; i < 8; i++) {
            int idx = tid + 256*i;
            int split = idx >> 10; int rem = idx & 1023;
            int kr = rem >> 6; int j = rem & 63;
            const u32* p = g_fs + ((size_t)(split*4 + b)*256 + ks*16 + kr)*8192 + p0w + j;
            u32 v = __ldg(p);
            *(u32*)(dst + split*4352 + kr*272 + j*4) = v;
        }
    };

    loadB(0, 0);
    __syncthreads();

    for (int ks = 0; ks < 16; ks++) {
        int buf = ks & 1;
        if (ks + 1 < 16) loadB(ks+1, buf^1);

        u32 a0[2][4];
        {
            const uint4* ap = (const uint4*)(g_cwf + (((size_t)ks*8 + wm*2)*32 + lane)*4);
            uint4 f0 = ap[0];
            uint4 f1 = ap[32];
            a0[0][0]=f0.x; a0[0][1]=f0.y; a0[0][2]=f0.z; a0[0][3]=f0.w;
            a0[1][0]=f1.x; a0[1][1]=f1.y; a0[1][2]=f1.z; a0[1][3]=f1.w;
        }

        int nsplits = is_wh ? 2 : 1;
        for (int sp = 0; sp < nsplits; sp++) {
            u32 bf[8][2];
            u32 base = sb + buf*8704 + sp*4352 + lm_k*272;
            #pragma unroll
            for (int li = 0; li < 4; li++) {
                int n = nw*64 + li*16 + lm_noff;
                u32 r0,r1,r2,r3;
                LDMATRIX_X4_TRANS(r0,r1,r2,r3, base + n*2);
                bf[2*li][0]=r0; bf[2*li][1]=r1; bf[2*li+1][0]=r2; bf[2*li+1][1]=r3;
            }
            #pragma unroll
            for (int mi = 0; mi < 2; mi++)
                #pragma unroll
                for (int ni = 0; ni < 8; ni++)
                    MMA_BF16(acc[mi][ni][0],acc[mi][ni][1],acc[mi][ni][2],acc[mi][ni][3],
                             a0[mi][0],a0[mi][1],a0[mi][2],a0[mi][3],
                             bf[ni][0],bf[ni][1]);
        }
        __syncthreads();
    }

    float* epi = (float*)sraw;
    if (!is_wh) {
        int pair = nw*2 + (wm - 2);
        #pragma unroll
        for (int mi = 0; mi < 2; mi++)
            #pragma unroll
            for (int ni = 0; ni < 8; ni++)
                *(float4*)&epi[pair*2048 + (mi*8+ni)*128 + lane*4] = *(float4*)acc[mi][ni];
    }
    __syncthreads();
    if (is_wh) {
        int pair = nw*2 + wm;
        #pragma unroll
        for (int mi = 0; mi < 2; mi++) {
            #pragma unroll
            for (int ni = 0; ni < 8; ni++) {
                float4 part = *(float4*)&epi[pair*2048 + (mi*8+ni)*128 + lane*4];
                int oc = wm*32 + mi*16 + (lane>>2);
                int px = nw*64 + ni*8 + (lane&3)*2;
                float bb0 = cb[oc];
                float bb8 = cb[oc + 8];
                float2 o0, o8;
                o0.x = fmaxf(acc[mi][ni][0] + part.x + bb0, 0.f);
                o0.y = fmaxf(acc[mi][ni][1] + part.y + bb0, 0.f);
                o8.x = fmaxf(acc[mi][ni][2] + part.z + bb8, 0.f);
                o8.y = fmaxf(acc[mi][ni][3] + part.w + bb8, 0.f);
                float* q0 = out + ((size_t)(b*64 + oc))*HW + p0w*2 + px;
                float* q8 = q0 + (size_t)8*HW;
                *(float2*)q0 = o0;
                *(float2*)q8 = o8;
            }
        }
    }
}

// ================= launch =================
extern "C" void kernel_launch(void* const* d_in, const int* in_sizes, int n_in,
                              void* d_out, int out_size)
{
    const float* x   = (const float*)d_in[0];
    const float* w1  = (const float*)d_in[1];
    const float* b1  = (const float*)d_in[2];
    const float* w2  = (const float*)d_in[3];
    const float* b2  = (const float*)d_in[4];
    const float* w3  = (const float*)d_in[5];
    const float* b3  = (const float*)d_in[6];
    const float* w4  = (const float*)d_in[7];
    const float* b4  = (const float*)d_in[8];
    const float* p_w = (const float*)d_in[9];
    const float* p_b = (const float*)d_in[10];
    const float* dw  = (const float*)d_in[11];
    const float* db  = (const float*)d_in[12];
    const float* cw  = (const float*)d_in[13];
    const float* cb  = (const float*)d_in[14];
    float* out = (float*)d_out;

    prep_kernel<<<4096, 256>>>(x, w1, w2, w3, w4, p_w, dw, cw, b1, b2, b3, b4);
    bconv_kernel<<<dim3(128, 4, 4), 256>>>();
    ytr_kernel<<<dim3(130, 16), 256>>>();
    offconv_kernel<<<dim3(128, 16), 256>>>(p_b);
    deform_kernel<<<dim3(2, 128, 16), 256>>>(db);
    final_kernel<<<dim3(128, 4), 256>>>(cb, out);
}